// round 3
// baseline (speedup 1.0000x reference)
#include <cuda_runtime.h>

#define B_  4
#define L_  2048
#define D_  1024
#define H_  16
#define DK_ 64

// Scratch (static __device__ — no allocation allowed in kernel_launch)
__device__ float g_Q [B_*H_*L_*DK_];   // [B,H,L,dk]
__device__ float g_K [B_*H_*L_*DK_];
__device__ float g_V [B_*H_*L_*DK_];
__device__ float g_AO[B_*L_*D_];       // attention output, [B,L,D]

// ---------------------------------------------------------------------------
// GEMM: C[m,n] = sum_k A[m,k] * B[n,k]   (both operands K-major, row-major)
// Tile 128x128xBK16, 256 threads, 8x8 per thread (2x2 groups of 4x4 for
// conflict-free float4 SMEM access). Register-staged double buffering.
// MODE 0: A = x, B selected by blockIdx.z in {Wq,Wk,Wv}, scatter to [B,H,L,dk]
// MODE 1: A = g_AO, B = W0 (=Wo), plain row-major store to Cout
// ---------------------------------------------------------------------------
template<int MODE>
__global__ __launch_bounds__(256, 2)
void gemm_kernel(const float* __restrict__ A,
                 const float* __restrict__ W0,
                 const float* __restrict__ W1,
                 const float* __restrict__ W2,
                 float* __restrict__ Cout)
{
    __shared__ float As[2][16*132];   // [k][m], padded stride 132
    __shared__ float Bs[2][16*132];   // [k][n]

    const int K   = D_;
    const int tid = threadIdx.x;
    const int tx  = tid & 15;
    const int ty  = tid >> 4;
    const int bm  = blockIdx.x;
    const int bn  = blockIdx.y;

    const float* Ap;
    const float* Bp;
    float*       Dst;
    if (MODE == 0) {
        Ap = A;
        const int z = blockIdx.z;
        Bp  = (z == 0) ? W0  : (z == 1) ? W1  : W2;
        Dst = (z == 0) ? g_Q : (z == 1) ? g_K : g_V;
    } else {
        Ap  = g_AO;
        Bp  = W0;
        Dst = Cout;
    }

    // Global->reg staging map: thread covers rows (tid>>2) and (tid>>2)+64,
    // k-group 4*(tid&3), one float4 each.
    const int lrow = tid >> 2;          // 0..63
    const int lk4  = (tid & 3) << 2;    // 0,4,8,12
    const float* Ald = Ap + (bm*128 + lrow)*K + lk4;
    const float* Bld = Bp + (bn*128 + lrow)*K + lk4;

    float4 ra0 = *(const float4*)(Ald);
    float4 ra1 = *(const float4*)(Ald + 64*K);
    float4 rb0 = *(const float4*)(Bld);
    float4 rb1 = *(const float4*)(Bld + 64*K);

    float acc[8][8];
#pragma unroll
    for (int i = 0; i < 8; i++)
#pragma unroll
        for (int j = 0; j < 8; j++) acc[i][j] = 0.f;

    {   // stage tile 0
        float* as = As[0]; float* bs = Bs[0];
#pragma unroll
        for (int c = 0; c < 4; c++) {
            as[(lk4+c)*132 + lrow]      = (&ra0.x)[c];
            as[(lk4+c)*132 + lrow + 64] = (&ra1.x)[c];
            bs[(lk4+c)*132 + lrow]      = (&rb0.x)[c];
            bs[(lk4+c)*132 + lrow + 64] = (&rb1.x)[c];
        }
    }
    __syncthreads();

    const int NT = K / 16;
    for (int kt = 0; kt < NT; kt++) {
        const int p = kt & 1;
        if (kt + 1 < NT) {  // prefetch next tile into registers
            const float* Ak = Ald + (kt+1)*16;
            const float* Bk = Bld + (kt+1)*16;
            ra0 = *(const float4*)(Ak);
            ra1 = *(const float4*)(Ak + 64*K);
            rb0 = *(const float4*)(Bk);
            rb1 = *(const float4*)(Bk + 64*K);
        }
        const float* as = As[p];
        const float* bs = Bs[p];
#pragma unroll
        for (int k = 0; k < 16; k++) {
            const float4 a0 = *(const float4*)(as + k*132 + 4*ty);
            const float4 a1 = *(const float4*)(as + k*132 + 64 + 4*ty);
            const float4 b0 = *(const float4*)(bs + k*132 + 4*tx);
            const float4 b1 = *(const float4*)(bs + k*132 + 64 + 4*tx);
            const float av[8] = {a0.x,a0.y,a0.z,a0.w,a1.x,a1.y,a1.z,a1.w};
            const float bv[8] = {b0.x,b0.y,b0.z,b0.w,b1.x,b1.y,b1.z,b1.w};
#pragma unroll
            for (int i = 0; i < 8; i++)
#pragma unroll
                for (int j = 0; j < 8; j++)
                    acc[i][j] = fmaf(av[i], bv[j], acc[i][j]);
        }
        if (kt + 1 < NT) {
            float* as2 = As[p^1]; float* bs2 = Bs[p^1];
#pragma unroll
            for (int c = 0; c < 4; c++) {
                as2[(lk4+c)*132 + lrow]      = (&ra0.x)[c];
                as2[(lk4+c)*132 + lrow + 64] = (&ra1.x)[c];
                bs2[(lk4+c)*132 + lrow]      = (&rb0.x)[c];
                bs2[(lk4+c)*132 + lrow + 64] = (&rb1.x)[c];
            }
        }
        __syncthreads();
    }

    // Epilogue
#pragma unroll
    for (int ig = 0; ig < 2; ig++)
#pragma unroll
    for (int i = 0; i < 4; i++) {
        const int m = bm*128 + ig*64 + 4*ty + i;
#pragma unroll
        for (int jg = 0; jg < 2; jg++) {
            const int n = bn*128 + jg*64 + 4*tx;
            const float4 v = make_float4(acc[ig*4+i][jg*4+0], acc[ig*4+i][jg*4+1],
                                         acc[ig*4+i][jg*4+2], acc[ig*4+i][jg*4+3]);
            if (MODE == 0) {
                const int b  = m >> 11;       // m = b*L + l
                const int l  = m & 2047;
                const int h  = n >> 6;        // n = h*dk + d
                const int dk = n & 63;
                *(float4*)(Dst + (((b*H_ + h)*L_ + l)*DK_ + dk)) = v;
            } else {
                *(float4*)(Dst + m*D_ + n) = v;
            }
        }
    }
}

// ---------------------------------------------------------------------------
// Fused causal flash-attention, fp32. One block = 64 queries of one (b,h).
// 256 threads as 16x16; thread owns 4x4 of S and 4x4 of O.
// Q pre-scaled by 1/sqrt(dk). K stored d-major in SMEM so the b-fragment of
// the S-GEMM is a conflict-free LDS.128; a-fragments are broadcasts.
// ---------------------------------------------------------------------------
__global__ __launch_bounds__(256, 2)
void attn_kernel()
{
    extern __shared__ float sm[];
    float* Qs  = sm;                  // [64][68]  (row r, col d)
    float* Kts = sm + 64*68;          // [64][68]  (row d, col key) -- transposed
    float* Vs  = sm + 2*64*68;        // [64][68]  (row key, col d)
    float* Ps  = sm + 3*64*68;        // [64][68]  (row q, col key)

    const int tid = threadIdx.x;
    const int tx  = tid & 15;
    const int ty  = tid >> 4;
    const int qb  = blockIdx.x;       // query tile 0..31
    const int bh  = blockIdx.y;       // 0..63

    const float* Qg = g_Q + (bh*L_ + qb*64)*DK_;
    const float* Kg = g_K + bh*L_*DK_;
    const float* Vg = g_V + bh*L_*DK_;

    const int lr = tid >> 4;          // 0..15
    const int ldc = (tid & 15) << 2;  // 0..60

    // Load + prescale Q tile
#pragma unroll
    for (int s = 0; s < 4; s++) {
        const int row = lr + 16*s;
        float4 v = *(const float4*)(Qg + row*64 + ldc);
        v.x *= 0.125f; v.y *= 0.125f; v.z *= 0.125f; v.w *= 0.125f;
        *(float4*)(Qs + row*68 + ldc) = v;
    }

    float O[4][4];
    float Mx[4], Ls[4];
#pragma unroll
    for (int i = 0; i < 4; i++) {
        Mx[i] = -1e30f; Ls[i] = 0.f;
#pragma unroll
        for (int j = 0; j < 4; j++) O[i][j] = 0.f;
    }

    // K/V register staging for software pipelining
    float4 kst[4], vst[4];
#pragma unroll
    for (int s = 0; s < 4; s++) {
        kst[s] = *(const float4*)(Kg + (lr + 16*s)*64 + ldc);
        vst[s] = *(const float4*)(Vg + (lr + 16*s)*64 + ldc);
    }

    for (int kb = 0; kb <= qb; kb++) {
        // stage current K (transposed) + V into SMEM
#pragma unroll
        for (int s = 0; s < 4; s++) {
            const int row = lr + 16*s;
            Kts[(ldc+0)*68 + row] = kst[s].x;
            Kts[(ldc+1)*68 + row] = kst[s].y;
            Kts[(ldc+2)*68 + row] = kst[s].z;
            Kts[(ldc+3)*68 + row] = kst[s].w;
            *(float4*)(Vs + row*68 + ldc) = vst[s];
        }
        __syncthreads();

        if (kb < qb) {  // prefetch next tile
            const int nb = (kb+1)*64;
#pragma unroll
            for (int s = 0; s < 4; s++) {
                kst[s] = *(const float4*)(Kg + (nb + lr + 16*s)*64 + ldc);
                vst[s] = *(const float4*)(Vg + (nb + lr + 16*s)*64 + ldc);
            }
        }

        // S = Q @ K^T (scaled)
        float S[4][4];
#pragma unroll
        for (int i = 0; i < 4; i++)
#pragma unroll
            for (int j = 0; j < 4; j++) S[i][j] = 0.f;

#pragma unroll
        for (int d0 = 0; d0 < 64; d0 += 4) {
            const float4 b0 = *(const float4*)(Kts + (d0+0)*68 + 4*tx);
            const float4 b1 = *(const float4*)(Kts + (d0+1)*68 + 4*tx);
            const float4 b2 = *(const float4*)(Kts + (d0+2)*68 + 4*tx);
            const float4 b3 = *(const float4*)(Kts + (d0+3)*68 + 4*tx);
#pragma unroll
            for (int i = 0; i < 4; i++) {
                const float4 a = *(const float4*)(Qs + (4*ty+i)*68 + d0);
                S[i][0] = fmaf(a.x,b0.x, fmaf(a.y,b1.x, fmaf(a.z,b2.x, fmaf(a.w,b3.x, S[i][0]))));
                S[i][1] = fmaf(a.x,b0.y, fmaf(a.y,b1.y, fmaf(a.z,b2.y, fmaf(a.w,b3.y, S[i][1]))));
                S[i][2] = fmaf(a.x,b0.z, fmaf(a.y,b1.z, fmaf(a.z,b2.z, fmaf(a.w,b3.z, S[i][2]))));
                S[i][3] = fmaf(a.x,b0.w, fmaf(a.y,b1.w, fmaf(a.z,b2.w, fmaf(a.w,b3.w, S[i][3]))));
            }
        }

        if (kb == qb) {  // diagonal tile: causal mask
            const int qg = qb*64 + 4*ty;
            const int kg = kb*64 + 4*tx;
#pragma unroll
            for (int i = 0; i < 4; i++)
#pragma unroll
                for (int j = 0; j < 4; j++)
                    if (kg + j > qg + i) S[i][j] = -1e30f;
        }

        // Online softmax (row reductions across the 16 tx lanes via shfl)
#pragma unroll
        for (int i = 0; i < 4; i++) {
            float m = fmaxf(fmaxf(S[i][0], S[i][1]), fmaxf(S[i][2], S[i][3]));
#pragma unroll
            for (int off = 8; off >= 1; off >>= 1)
                m = fmaxf(m, __shfl_xor_sync(0xffffffffu, m, off));
            const float mn  = fmaxf(Mx[i], m);
            const float fac = __expf(Mx[i] - mn);
            Mx[i] = mn;
            float rs = 0.f;
#pragma unroll
            for (int j = 0; j < 4; j++) {
                S[i][j] = __expf(S[i][j] - mn);
                rs += S[i][j];
            }
#pragma unroll
            for (int off = 8; off >= 1; off >>= 1)
                rs += __shfl_xor_sync(0xffffffffu, rs, off);
            Ls[i] = Ls[i]*fac + rs;
#pragma unroll
            for (int j = 0; j < 4; j++) O[i][j] *= fac;
            *(float4*)(Ps + (4*ty+i)*68 + 4*tx) = make_float4(S[i][0], S[i][1], S[i][2], S[i][3]);
        }
        __syncthreads();

        // O += P @ V
#pragma unroll
        for (int k0 = 0; k0 < 64; k0 += 4) {
            const float4 b0 = *(const float4*)(Vs + (k0+0)*68 + 4*tx);
            const float4 b1 = *(const float4*)(Vs + (k0+1)*68 + 4*tx);
            const float4 b2 = *(const float4*)(Vs + (k0+2)*68 + 4*tx);
            const float4 b3 = *(const float4*)(Vs + (k0+3)*68 + 4*tx);
#pragma unroll
            for (int i = 0; i < 4; i++) {
                const float4 a = *(const float4*)(Ps + (4*ty+i)*68 + k0);
                O[i][0] = fmaf(a.x,b0.x, fmaf(a.y,b1.x, fmaf(a.z,b2.x, fmaf(a.w,b3.x, O[i][0]))));
                O[i][1] = fmaf(a.x,b0.y, fmaf(a.y,b1.y, fmaf(a.z,b2.y, fmaf(a.w,b3.y, O[i][1]))));
                O[i][2] = fmaf(a.x,b0.z, fmaf(a.y,b1.z, fmaf(a.z,b2.z, fmaf(a.w,b3.z, O[i][2]))));
                O[i][3] = fmaf(a.x,b0.w, fmaf(a.y,b1.w, fmaf(a.z,b2.w, fmaf(a.w,b3.w, O[i][3]))));
            }
        }
        __syncthreads();
    }

    // Normalize and write [B,L,D]
    const int b = bh >> 4;
    const int h = bh & 15;
#pragma unroll
    for (int i = 0; i < 4; i++) {
        const float inv = 1.0f / Ls[i];
        const int q = qb*64 + 4*ty + i;
        const float4 v = make_float4(O[i][0]*inv, O[i][1]*inv, O[i][2]*inv, O[i][3]*inv);
        *(float4*)(g_AO + (b*L_ + q)*D_ + h*64 + 4*tx) = v;
    }
}

// ---------------------------------------------------------------------------
extern "C" void kernel_launch(void* const* d_in, const int* in_sizes, int n_in,
                              void* d_out, int out_size)
{
    const float* x  = (const float*)d_in[0];
    const float* Wq = (const float*)d_in[1];
    const float* Wk = (const float*)d_in[2];
    const float* Wv = (const float*)d_in[3];
    const float* Wo = (const float*)d_in[4];
    float* out = (float*)d_out;

    const int attn_smem = 4 * 64 * 68 * (int)sizeof(float);  // 69,632 B
    cudaFuncSetAttribute(attn_kernel,
                         cudaFuncAttributeMaxDynamicSharedMemorySize, attn_smem);

    // Q/K/V projections (z selects weight + destination)
    gemm_kernel<0><<<dim3(64, 8, 3), 256>>>(x, Wq, Wk, Wv, nullptr);
    // Fused causal attention
    attn_kernel<<<dim3(32, 64), 256, attn_smem>>>();
    // Output projection
    gemm_kernel<1><<<dim3(64, 8, 1), 256>>>(nullptr, Wo, nullptr, nullptr, out);
}

// round 6
// speedup vs baseline: 1.4055x; 1.4055x over previous
#include <cuda_runtime.h>
#include <cuda_bf16.h>
#include <cstdint>

#define B_  4
#define L_  2048
#define D_  1024
#define H_  16
#define DK_ 64

// ---------------------------------------------------------------------------
// Scratch (static __device__ — no allocation allowed)
// ---------------------------------------------------------------------------
__device__ float g_Q [B_*H_*L_*DK_];   // [B,H,L,dk] fp32
__device__ float g_K [B_*H_*L_*DK_];
__device__ float g_V [B_*H_*L_*DK_];
__device__ float g_AO[B_*L_*D_];       // attention output fp32

__device__ __nv_bfloat16 g_xh [B_*L_*D_];
__device__ __nv_bfloat16 g_xl [B_*L_*D_];
__device__ __nv_bfloat16 g_Wh [4*D_*D_];   // Wq,Wk,Wv,Wo hi
__device__ __nv_bfloat16 g_Wl [4*D_*D_];
__device__ __nv_bfloat16 g_aoh[B_*L_*D_];
__device__ __nv_bfloat16 g_aol[B_*L_*D_];

// ---------------------------------------------------------------------------
// PTX helpers (compute_100-safe: ldmatrix / mma.sync / cp.async only)
// ---------------------------------------------------------------------------
__device__ __forceinline__ uint32_t smem_u32(const void* p) {
    uint32_t a;
    asm("{ .reg .u64 t; cvta.to.shared.u64 t, %1; cvt.u32.u64 %0, t; }"
        : "=r"(a) : "l"(p));
    return a;
}
__device__ __forceinline__ void ldmx4(uint32_t* r, uint32_t a) {
    asm volatile("ldmatrix.sync.aligned.m8n8.x4.shared.b16 {%0,%1,%2,%3}, [%4];"
                 : "=r"(r[0]), "=r"(r[1]), "=r"(r[2]), "=r"(r[3]) : "r"(a));
}
__device__ __forceinline__ void mma16816(float* c, const uint32_t* a, const uint32_t* b) {
    asm volatile("mma.sync.aligned.m16n8k16.row.col.f32.bf16.bf16.f32 "
                 "{%0,%1,%2,%3}, {%4,%5,%6,%7}, {%8,%9}, {%0,%1,%2,%3};"
                 : "+f"(c[0]), "+f"(c[1]), "+f"(c[2]), "+f"(c[3])
                 : "r"(a[0]), "r"(a[1]), "r"(a[2]), "r"(a[3]),
                   "r"(b[0]), "r"(b[1]));
}
__device__ __forceinline__ void cpa16(uint32_t s, const void* g) {
    asm volatile("cp.async.cg.shared.global [%0], [%1], 16;"
                 :: "r"(s), "l"(__cvta_generic_to_global(g)));
}

// ---------------------------------------------------------------------------
// bf16 hi/lo split:  hi = bf16(x), lo = bf16(x - hi)
// sel: 0=x, 1..4=Wq/Wk/Wv/Wo, 5=g_AO
// ---------------------------------------------------------------------------
__global__ void split_kernel(const float* __restrict__ src, int sel, int n4)
{
    int i = blockIdx.x * blockDim.x + threadIdx.x;
    if (i >= n4) return;
    __nv_bfloat16 *hi, *lo;
    const float* s = src;
    if (sel == 0)      { hi = g_xh;  lo = g_xl; }
    else if (sel <= 4) { hi = g_Wh + (size_t)(sel-1)*D_*D_;
                         lo = g_Wl + (size_t)(sel-1)*D_*D_; }
    else               { hi = g_aoh; lo = g_aol; s = g_AO; }

    float4 v = ((const float4*)s)[i];
    __nv_bfloat16 h0 = __float2bfloat16(v.x);
    __nv_bfloat16 h1 = __float2bfloat16(v.y);
    __nv_bfloat16 h2 = __float2bfloat16(v.z);
    __nv_bfloat16 h3 = __float2bfloat16(v.w);
    __nv_bfloat16 l0 = __float2bfloat16(v.x - __bfloat162float(h0));
    __nv_bfloat16 l1 = __float2bfloat16(v.y - __bfloat162float(h1));
    __nv_bfloat16 l2 = __float2bfloat16(v.z - __bfloat162float(h2));
    __nv_bfloat16 l3 = __float2bfloat16(v.w - __bfloat162float(h3));
    ((__nv_bfloat162*)hi)[2*i]   = __halves2bfloat162(h0, h1);
    ((__nv_bfloat162*)hi)[2*i+1] = __halves2bfloat162(h2, h3);
    ((__nv_bfloat162*)lo)[2*i]   = __halves2bfloat162(l0, l1);
    ((__nv_bfloat162*)lo)[2*i+1] = __halves2bfloat162(l2, l3);
}

// ---------------------------------------------------------------------------
// HMMA bf16-split GEMM:  C[m,n] = sum_k A[m,k] * W[n,k]
// CTA 128x128, K-tile 32, cp.async double-buffered. 8 warps, warp tile 64x32.
// Per k16-step: 16x (AhBh) + 16x (AhBl) + 16x (AlBh) mma.m16n8k16.
// SMEM rows padded to 80B -> conflict-free ldmatrix (banks 20r+4c mod 32).
// MODE 0: A = x(split), W by blockIdx.z; scatter fp32 to g_Q/g_K/g_V.
// MODE 1: A = AO(split), W = Wo; row-major fp32 to Cout.
// ---------------------------------------------------------------------------
#define ROWB   80                       // bytes per 32-bf16 SMEM row
#define OFF_AH 0
#define OFF_AL (128*ROWB)               // 10240
#define OFF_BH (2*128*ROWB)             // 20480
#define OFF_BL (3*128*ROWB)             // 30720
#define STAGE  (4*128*ROWB)             // 40960
#define GEMM_SMEM (2*STAGE)             // 81920

template<int MODE>
__global__ __launch_bounds__(256)
void gemm_hmma(float* __restrict__ Cout)
{
    extern __shared__ char smem[];
    const uint32_t sb = smem_u32(smem);
    const int tid  = threadIdx.x;
    const int wid  = tid >> 5;
    const int lane = tid & 31;
    const int bm   = blockIdx.x;
    const int bn   = blockIdx.y;
    const int z    = (MODE == 0) ? blockIdx.z : 3;

    const __nv_bfloat16* Agh = (MODE == 0) ? g_xh : g_aoh;
    const __nv_bfloat16* Agl = (MODE == 0) ? g_xl : g_aol;
    const __nv_bfloat16* Wgh = g_Wh + (size_t)z * D_ * D_;
    const __nv_bfloat16* Wgl = g_Wl + (size_t)z * D_ * D_;

    const int mbase = bm * 128;
    const int nbase = bn * 128;

    // warp tiling: wm in {0,1} -> 64-row half; wn in {0..3} -> 32-col quarter
    const int wm = wid >> 2;
    const int wn = wid & 3;

    // per-lane ldmatrix addressing (lane i supplies tile i>>3, row i&7)
    const int t  = lane >> 3;
    const int ri = lane & 7;
    const uint32_t aLane = (uint32_t)((wm*64 + (t&1)*8 + ri) * ROWB + (t>>1)*16);
    const uint32_t bLane = (uint32_t)((wn*32 + (t>>1)*8 + ri) * ROWB + (t&1)*16);

    // global staging map: 2 uint4 per matrix per thread per K-tile
    const int grow0 = tid >> 2;            // idx 0..255 -> rows 0..63
    const int gc    = (tid & 3);           // 16B chunk 0..3
    const uint32_t so0 = (uint32_t)(grow0 * ROWB + gc * 16);
    const uint32_t so1 = so0 + 64u * ROWB;

    float acc[4][4][4];
#pragma unroll
    for (int i = 0; i < 4; i++)
#pragma unroll
        for (int j = 0; j < 4; j++)
#pragma unroll
            for (int q = 0; q < 4; q++) acc[i][j][q] = 0.f;

    const int NT = D_ / 32;                // 32 K-tiles

    // ---- stage issuer ----
    auto issue_stage = [&](int kt) {
        const uint32_t st = sb + (uint32_t)(kt & 1) * STAGE;
        const int kcol = kt * 32;
        const size_t ga0 = (size_t)(mbase + grow0) * D_ + kcol + gc * 8;
        const size_t ga1 = ga0 + (size_t)64 * D_;
        const size_t gb0 = (size_t)(nbase + grow0) * D_ + kcol + gc * 8;
        const size_t gb1 = gb0 + (size_t)64 * D_;
        cpa16(st + OFF_AH + so0, Agh + ga0);
        cpa16(st + OFF_AH + so1, Agh + ga1);
        cpa16(st + OFF_AL + so0, Agl + ga0);
        cpa16(st + OFF_AL + so1, Agl + ga1);
        cpa16(st + OFF_BH + so0, Wgh + gb0);
        cpa16(st + OFF_BH + so1, Wgh + gb1);
        cpa16(st + OFF_BL + so0, Wgl + gb0);
        cpa16(st + OFF_BL + so1, Wgl + gb1);
        asm volatile("cp.async.commit_group;" ::: "memory");
    };

    issue_stage(0);

    for (int kt = 0; kt < NT; kt++) {
        if (kt + 1 < NT) {
            issue_stage(kt + 1);
            asm volatile("cp.async.wait_group 1;" ::: "memory");
        } else {
            asm volatile("cp.async.wait_group 0;" ::: "memory");
        }
        __syncthreads();

        const uint32_t st = sb + (uint32_t)(kt & 1) * STAGE;

#pragma unroll
        for (int ks = 0; ks < 2; ks++) {
            const uint32_t ko = (uint32_t)(ks * 32);   // 2 chunks of 16B per k16

            uint32_t Ah[4][4], Bh[2][4], Bl[2][4];
#pragma unroll
            for (int mf = 0; mf < 4; mf++)
                ldmx4(Ah[mf], st + OFF_AH + aLane + (uint32_t)(mf*16*ROWB) + ko);
#pragma unroll
            for (int g = 0; g < 2; g++)
                ldmx4(Bh[g], st + OFF_BH + bLane + (uint32_t)(g*16*ROWB) + ko);
#pragma unroll
            for (int g = 0; g < 2; g++)
                ldmx4(Bl[g], st + OFF_BL + bLane + (uint32_t)(g*16*ROWB) + ko);

            // Ah * Bh
#pragma unroll
            for (int mf = 0; mf < 4; mf++)
#pragma unroll
                for (int nf = 0; nf < 4; nf++)
                    mma16816(acc[mf][nf], Ah[mf], &Bh[nf >> 1][(nf & 1) * 2]);
            // Ah * Bl
#pragma unroll
            for (int mf = 0; mf < 4; mf++)
#pragma unroll
                for (int nf = 0; nf < 4; nf++)
                    mma16816(acc[mf][nf], Ah[mf], &Bl[nf >> 1][(nf & 1) * 2]);
            // Al * Bh (reuse Ah storage)
#pragma unroll
            for (int mf = 0; mf < 4; mf++)
                ldmx4(Ah[mf], st + OFF_AL + aLane + (uint32_t)(mf*16*ROWB) + ko);
#pragma unroll
            for (int mf = 0; mf < 4; mf++)
#pragma unroll
                for (int nf = 0; nf < 4; nf++)
                    mma16816(acc[mf][nf], Ah[mf], &Bh[nf >> 1][(nf & 1) * 2]);
        }
        __syncthreads();
    }

    // ---- epilogue ----
    const int l4 = lane >> 2;
    const int l2 = (lane & 3) * 2;
#pragma unroll
    for (int mf = 0; mf < 4; mf++) {
#pragma unroll
        for (int half = 0; half < 2; half++) {
            const int m = mbase + wm*64 + mf*16 + half*8 + l4;
#pragma unroll
            for (int nf = 0; nf < 4; nf++) {
                const int n  = nbase + wn*32 + nf*8 + l2;
                const float c0 = acc[mf][nf][half*2 + 0];
                const float c1 = acc[mf][nf][half*2 + 1];
                if (MODE == 0) {
                    const int b  = m >> 11;
                    const int lr = m & 2047;
                    const int h  = n >> 6;
                    const int dk = n & 63;
                    float* dstbase = (z == 0) ? g_Q : (z == 1) ? g_K : g_V;
                    *(float2*)(dstbase + ((size_t)(b*H_ + h)*L_ + lr)*DK_ + dk) =
                        make_float2(c0, c1);
                } else {
                    *(float2*)(Cout + (size_t)m * D_ + n) = make_float2(c0, c1);
                }
            }
        }
    }
}

// ---------------------------------------------------------------------------
// Fused causal flash-attention, fp32 (unchanged — passes at 1e-6).
// ---------------------------------------------------------------------------
__global__ __launch_bounds__(256, 2)
void attn_kernel()
{
    extern __shared__ float sm[];
    float* Qs  = sm;
    float* Kts = sm + 64*68;
    float* Vs  = sm + 2*64*68;
    float* Ps  = sm + 3*64*68;

    const int tid = threadIdx.x;
    const int tx  = tid & 15;
    const int ty  = tid >> 4;
    const int qb  = blockIdx.x;
    const int bh  = blockIdx.y;

    const float* Qg = g_Q + (bh*L_ + qb*64)*DK_;
    const float* Kg = g_K + bh*L_*DK_;
    const float* Vg = g_V + bh*L_*DK_;

    const int lr = tid >> 4;
    const int ldc = (tid & 15) << 2;

#pragma unroll
    for (int s = 0; s < 4; s++) {
        const int row = lr + 16*s;
        float4 v = *(const float4*)(Qg + row*64 + ldc);
        v.x *= 0.125f; v.y *= 0.125f; v.z *= 0.125f; v.w *= 0.125f;
        *(float4*)(Qs + row*68 + ldc) = v;
    }

    float O[4][4];
    float Mx[4], Ls[4];
#pragma unroll
    for (int i = 0; i < 4; i++) {
        Mx[i] = -1e30f; Ls[i] = 0.f;
#pragma unroll
        for (int j = 0; j < 4; j++) O[i][j] = 0.f;
    }

    float4 kst[4], vst[4];
#pragma unroll
    for (int s = 0; s < 4; s++) {
        kst[s] = *(const float4*)(Kg + (lr + 16*s)*64 + ldc);
        vst[s] = *(const float4*)(Vg + (lr + 16*s)*64 + ldc);
    }

    for (int kb = 0; kb <= qb; kb++) {
#pragma unroll
        for (int s = 0; s < 4; s++) {
            const int row = lr + 16*s;
            Kts[(ldc+0)*68 + row] = kst[s].x;
            Kts[(ldc+1)*68 + row] = kst[s].y;
            Kts[(ldc+2)*68 + row] = kst[s].z;
            Kts[(ldc+3)*68 + row] = kst[s].w;
            *(float4*)(Vs + row*68 + ldc) = vst[s];
        }
        __syncthreads();

        if (kb < qb) {
            const int nb = (kb+1)*64;
#pragma unroll
            for (int s = 0; s < 4; s++) {
                kst[s] = *(const float4*)(Kg + (nb + lr + 16*s)*64 + ldc);
                vst[s] = *(const float4*)(Vg + (nb + lr + 16*s)*64 + ldc);
            }
        }

        float S[4][4];
#pragma unroll
        for (int i = 0; i < 4; i++)
#pragma unroll
            for (int j = 0; j < 4; j++) S[i][j] = 0.f;

#pragma unroll
        for (int d0 = 0; d0 < 64; d0 += 4) {
            const float4 b0 = *(const float4*)(Kts + (d0+0)*68 + 4*tx);
            const float4 b1 = *(const float4*)(Kts + (d0+1)*68 + 4*tx);
            const float4 b2 = *(const float4*)(Kts + (d0+2)*68 + 4*tx);
            const float4 b3 = *(const float4*)(Kts + (d0+3)*68 + 4*tx);
#pragma unroll
            for (int i = 0; i < 4; i++) {
                const float4 a = *(const float4*)(Qs + (4*ty+i)*68 + d0);
                S[i][0] = fmaf(a.x,b0.x, fmaf(a.y,b1.x, fmaf(a.z,b2.x, fmaf(a.w,b3.x, S[i][0]))));
                S[i][1] = fmaf(a.x,b0.y, fmaf(a.y,b1.y, fmaf(a.z,b2.y, fmaf(a.w,b3.y, S[i][1]))));
                S[i][2] = fmaf(a.x,b0.z, fmaf(a.y,b1.z, fmaf(a.z,b2.z, fmaf(a.w,b3.z, S[i][2]))));
                S[i][3] = fmaf(a.x,b0.w, fmaf(a.y,b1.w, fmaf(a.z,b2.w, fmaf(a.w,b3.w, S[i][3]))));
            }
        }

        if (kb == qb) {
            const int qg = qb*64 + 4*ty;
            const int kg = kb*64 + 4*tx;
#pragma unroll
            for (int i = 0; i < 4; i++)
#pragma unroll
                for (int j = 0; j < 4; j++)
                    if (kg + j > qg + i) S[i][j] = -1e30f;
        }

#pragma unroll
        for (int i = 0; i < 4; i++) {
            float m = fmaxf(fmaxf(S[i][0], S[i][1]), fmaxf(S[i][2], S[i][3]));
#pragma unroll
            for (int off = 8; off >= 1; off >>= 1)
                m = fmaxf(m, __shfl_xor_sync(0xffffffffu, m, off));
            const float mn  = fmaxf(Mx[i], m);
            const float fac = __expf(Mx[i] - mn);
            Mx[i] = mn;
            float rs = 0.f;
#pragma unroll
            for (int j = 0; j < 4; j++) {
                S[i][j] = __expf(S[i][j] - mn);
                rs += S[i][j];
            }
#pragma unroll
            for (int off = 8; off >= 1; off >>= 1)
                rs += __shfl_xor_sync(0xffffffffu, rs, off);
            Ls[i] = Ls[i]*fac + rs;
#pragma unroll
            for (int j = 0; j < 4; j++) O[i][j] *= fac;
            *(float4*)(Ps + (4*ty+i)*68 + 4*tx) = make_float4(S[i][0], S[i][1], S[i][2], S[i][3]);
        }
        __syncthreads();

#pragma unroll
        for (int k0 = 0; k0 < 64; k0 += 4) {
            const float4 b0 = *(const float4*)(Vs + (k0+0)*68 + 4*tx);
            const float4 b1 = *(const float4*)(Vs + (k0+1)*68 + 4*tx);
            const float4 b2 = *(const float4*)(Vs + (k0+2)*68 + 4*tx);
            const float4 b3 = *(const float4*)(Vs + (k0+3)*68 + 4*tx);
#pragma unroll
            for (int i = 0; i < 4; i++) {
                const float4 a = *(const float4*)(Ps + (4*ty+i)*68 + k0);
                O[i][0] = fmaf(a.x,b0.x, fmaf(a.y,b1.x, fmaf(a.z,b2.x, fmaf(a.w,b3.x, O[i][0]))));
                O[i][1] = fmaf(a.x,b0.y, fmaf(a.y,b1.y, fmaf(a.z,b2.y, fmaf(a.w,b3.y, O[i][1]))));
                O[i][2] = fmaf(a.x,b0.z, fmaf(a.y,b1.z, fmaf(a.z,b2.z, fmaf(a.w,b3.z, O[i][2]))));
                O[i][3] = fmaf(a.x,b0.w, fmaf(a.y,b1.w, fmaf(a.z,b2.w, fmaf(a.w,b3.w, O[i][3]))));
            }
        }
        __syncthreads();
    }

    const int b = bh >> 4;
    const int h = bh & 15;
#pragma unroll
    for (int i = 0; i < 4; i++) {
        const float inv = 1.0f / Ls[i];
        const int q = qb*64 + 4*ty + i;
        const float4 v = make_float4(O[i][0]*inv, O[i][1]*inv, O[i][2]*inv, O[i][3]*inv);
        *(float4*)(g_AO + (b*L_ + q)*D_ + h*64 + 4*tx) = v;
    }
}

// ---------------------------------------------------------------------------
extern "C" void kernel_launch(void* const* d_in, const int* in_sizes, int n_in,
                              void* d_out, int out_size)
{
    const float* x  = (const float*)d_in[0];
    const float* Wq = (const float*)d_in[1];
    const float* Wk = (const float*)d_in[2];
    const float* Wv = (const float*)d_in[3];
    const float* Wo = (const float*)d_in[4];
    float* out = (float*)d_out;

    const int attn_smem = 4 * 64 * 68 * (int)sizeof(float);
    cudaFuncSetAttribute(attn_kernel,
                         cudaFuncAttributeMaxDynamicSharedMemorySize, attn_smem);
    cudaFuncSetAttribute(gemm_hmma<0>,
                         cudaFuncAttributeMaxDynamicSharedMemorySize, GEMM_SMEM);
    cudaFuncSetAttribute(gemm_hmma<1>,
                         cudaFuncAttributeMaxDynamicSharedMemorySize, GEMM_SMEM);

    const int n4x = (B_*L_*D_) / 4;
    const int n4w = (D_*D_) / 4;

    // bf16 hi/lo splits of inputs
    split_kernel<<<(n4x + 255)/256, 256>>>(x,  0, n4x);
    split_kernel<<<(n4w + 255)/256, 256>>>(Wq, 1, n4w);
    split_kernel<<<(n4w + 255)/256, 256>>>(Wk, 2, n4w);
    split_kernel<<<(n4w + 255)/256, 256>>>(Wv, 3, n4w);
    split_kernel<<<(n4w + 255)/256, 256>>>(Wo, 4, n4w);

    // Q/K/V projections on HMMA tensor cores (bf16 2-term split)
    gemm_hmma<0><<<dim3(64, 8, 3), 256, GEMM_SMEM>>>(nullptr);

    // Fused causal attention (fp32)
    attn_kernel<<<dim3(32, 64), 256, attn_smem>>>();

    // Split attention output, then O-projection on HMMA
    split_kernel<<<(n4x + 255)/256, 256>>>(nullptr, 5, n4x);
    gemm_hmma<1><<<dim3(64, 8, 1), 256, GEMM_SMEM>>>(out);
}

// round 7
// speedup vs baseline: 2.3294x; 1.6574x over previous
#include <cuda_runtime.h>
#include <cuda_bf16.h>
#include <cstdint>

#define B_  4
#define L_  2048
#define D_  1024
#define H_  16
#define DK_ 64

// ---------------------------------------------------------------------------
// Scratch (static __device__ — no allocation allowed)
// ---------------------------------------------------------------------------
__device__ __nv_bfloat16 g_xh [B_*L_*D_];
__device__ __nv_bfloat16 g_xl [B_*L_*D_];
__device__ __nv_bfloat16 g_Wh [4*D_*D_];   // Wq,Wk,Wv,Wo hi
__device__ __nv_bfloat16 g_Wl [4*D_*D_];
__device__ __nv_bfloat16 g_aoh[B_*L_*D_];
__device__ __nv_bfloat16 g_aol[B_*L_*D_];
// Q/K/V as bf16 hi/lo pairs, layout [B,H,L,dk]
__device__ __nv_bfloat16 g_Qh[B_*H_*L_*DK_];
__device__ __nv_bfloat16 g_Ql[B_*H_*L_*DK_];
__device__ __nv_bfloat16 g_Kh[B_*H_*L_*DK_];
__device__ __nv_bfloat16 g_Kl[B_*H_*L_*DK_];
__device__ __nv_bfloat16 g_Vh[B_*H_*L_*DK_];
__device__ __nv_bfloat16 g_Vl[B_*H_*L_*DK_];

// ---------------------------------------------------------------------------
// PTX helpers (compute_100-safe)
// ---------------------------------------------------------------------------
__device__ __forceinline__ uint32_t smem_u32(const void* p) {
    uint32_t a;
    asm("{ .reg .u64 t; cvta.to.shared.u64 t, %1; cvt.u32.u64 %0, t; }"
        : "=r"(a) : "l"(p));
    return a;
}
__device__ __forceinline__ void ldmx4(uint32_t* r, uint32_t a) {
    asm volatile("ldmatrix.sync.aligned.m8n8.x4.shared.b16 {%0,%1,%2,%3}, [%4];"
                 : "=r"(r[0]), "=r"(r[1]), "=r"(r[2]), "=r"(r[3]) : "r"(a));
}
__device__ __forceinline__ void ldmx4t(uint32_t* r, uint32_t a) {
    asm volatile("ldmatrix.sync.aligned.m8n8.x4.trans.shared.b16 {%0,%1,%2,%3}, [%4];"
                 : "=r"(r[0]), "=r"(r[1]), "=r"(r[2]), "=r"(r[3]) : "r"(a));
}
__device__ __forceinline__ void mma16816(float* c, const uint32_t* a, const uint32_t* b) {
    asm volatile("mma.sync.aligned.m16n8k16.row.col.f32.bf16.bf16.f32 "
                 "{%0,%1,%2,%3}, {%4,%5,%6,%7}, {%8,%9}, {%0,%1,%2,%3};"
                 : "+f"(c[0]), "+f"(c[1]), "+f"(c[2]), "+f"(c[3])
                 : "r"(a[0]), "r"(a[1]), "r"(a[2]), "r"(a[3]),
                   "r"(b[0]), "r"(b[1]));
}
__device__ __forceinline__ void cpa16(uint32_t s, const void* g) {
    asm volatile("cp.async.cg.shared.global [%0], [%1], 16;"
                 :: "r"(s), "l"(__cvta_generic_to_global(g)));
}
// pack two fp32 -> bf16x2, lo in low half
__device__ __forceinline__ uint32_t bfpack(float lo, float hi) {
    uint32_t d;
    asm("cvt.rn.bf16x2.f32 %0, %1, %2;" : "=r"(d) : "f"(hi), "f"(lo));
    return d;
}
__device__ __forceinline__ float2 bfunpack(uint32_t u) {
    __nv_bfloat162 t = *reinterpret_cast<__nv_bfloat162*>(&u);
    return make_float2(__bfloat162float(t.x), __bfloat162float(t.y));
}

// ---------------------------------------------------------------------------
// bf16 hi/lo split of inputs: sel 0=x, 1..4=Wq/Wk/Wv/Wo
// ---------------------------------------------------------------------------
__global__ void split_kernel(const float* __restrict__ src, int sel, int n4)
{
    int i = blockIdx.x * blockDim.x + threadIdx.x;
    if (i >= n4) return;
    __nv_bfloat16 *hi, *lo;
    if (sel == 0) { hi = g_xh; lo = g_xl; }
    else          { hi = g_Wh + (size_t)(sel-1)*D_*D_;
                    lo = g_Wl + (size_t)(sel-1)*D_*D_; }

    float4 v = ((const float4*)src)[i];
    __nv_bfloat16 h0 = __float2bfloat16(v.x);
    __nv_bfloat16 h1 = __float2bfloat16(v.y);
    __nv_bfloat16 h2 = __float2bfloat16(v.z);
    __nv_bfloat16 h3 = __float2bfloat16(v.w);
    __nv_bfloat16 l0 = __float2bfloat16(v.x - __bfloat162float(h0));
    __nv_bfloat16 l1 = __float2bfloat16(v.y - __bfloat162float(h1));
    __nv_bfloat16 l2 = __float2bfloat16(v.z - __bfloat162float(h2));
    __nv_bfloat16 l3 = __float2bfloat16(v.w - __bfloat162float(h3));
    ((__nv_bfloat162*)hi)[2*i]   = __halves2bfloat162(h0, h1);
    ((__nv_bfloat162*)hi)[2*i+1] = __halves2bfloat162(h2, h3);
    ((__nv_bfloat162*)lo)[2*i]   = __halves2bfloat162(l0, l1);
    ((__nv_bfloat162*)lo)[2*i+1] = __halves2bfloat162(l2, l3);
}

// ---------------------------------------------------------------------------
// HMMA bf16-split GEMM (verified R5). MODE 0: out = split bf16 Q/K/V
// (Q pre-scaled by 0.125*log2e). MODE 1: AO(split) @ Wo -> fp32 Cout.
// ---------------------------------------------------------------------------
#define ROWB   80
#define OFF_AH 0
#define OFF_AL (128*ROWB)
#define OFF_BH (2*128*ROWB)
#define OFF_BL (3*128*ROWB)
#define STAGE  (4*128*ROWB)
#define GEMM_SMEM (2*STAGE)

#define QSCALE 0.18033688011112042f   // 0.125 * log2(e)

template<int MODE>
__global__ __launch_bounds__(256)
void gemm_hmma(float* __restrict__ Cout)
{
    extern __shared__ char smem[];
    const uint32_t sb = smem_u32(smem);
    const int tid  = threadIdx.x;
    const int wid  = tid >> 5;
    const int lane = tid & 31;
    const int bm   = blockIdx.x;
    const int bn   = blockIdx.y;
    const int z    = (MODE == 0) ? blockIdx.z : 3;

    const __nv_bfloat16* Agh = (MODE == 0) ? g_xh : g_aoh;
    const __nv_bfloat16* Agl = (MODE == 0) ? g_xl : g_aol;
    const __nv_bfloat16* Wgh = g_Wh + (size_t)z * D_ * D_;
    const __nv_bfloat16* Wgl = g_Wl + (size_t)z * D_ * D_;

    const int mbase = bm * 128;
    const int nbase = bn * 128;
    const int wm = wid >> 2;
    const int wn = wid & 3;

    const int t  = lane >> 3;
    const int ri = lane & 7;
    const uint32_t aLane = (uint32_t)((wm*64 + (t&1)*8 + ri) * ROWB + (t>>1)*16);
    const uint32_t bLane = (uint32_t)((wn*32 + (t>>1)*8 + ri) * ROWB + (t&1)*16);

    const int grow0 = tid >> 2;
    const int gc    = (tid & 3);
    const uint32_t so0 = (uint32_t)(grow0 * ROWB + gc * 16);
    const uint32_t so1 = so0 + 64u * ROWB;

    float acc[4][4][4];
#pragma unroll
    for (int i = 0; i < 4; i++)
#pragma unroll
        for (int j = 0; j < 4; j++)
#pragma unroll
            for (int q = 0; q < 4; q++) acc[i][j][q] = 0.f;

    const int NT = D_ / 32;

    auto issue_stage = [&](int kt) {
        const uint32_t st = sb + (uint32_t)(kt & 1) * STAGE;
        const int kcol = kt * 32;
        const size_t ga0 = (size_t)(mbase + grow0) * D_ + kcol + gc * 8;
        const size_t ga1 = ga0 + (size_t)64 * D_;
        const size_t gb0 = (size_t)(nbase + grow0) * D_ + kcol + gc * 8;
        const size_t gb1 = gb0 + (size_t)64 * D_;
        cpa16(st + OFF_AH + so0, Agh + ga0);
        cpa16(st + OFF_AH + so1, Agh + ga1);
        cpa16(st + OFF_AL + so0, Agl + ga0);
        cpa16(st + OFF_AL + so1, Agl + ga1);
        cpa16(st + OFF_BH + so0, Wgh + gb0);
        cpa16(st + OFF_BH + so1, Wgh + gb1);
        cpa16(st + OFF_BL + so0, Wgl + gb0);
        cpa16(st + OFF_BL + so1, Wgl + gb1);
        asm volatile("cp.async.commit_group;" ::: "memory");
    };

    issue_stage(0);

    for (int kt = 0; kt < NT; kt++) {
        if (kt + 1 < NT) {
            issue_stage(kt + 1);
            asm volatile("cp.async.wait_group 1;" ::: "memory");
        } else {
            asm volatile("cp.async.wait_group 0;" ::: "memory");
        }
        __syncthreads();

        const uint32_t st = sb + (uint32_t)(kt & 1) * STAGE;

#pragma unroll
        for (int ks = 0; ks < 2; ks++) {
            const uint32_t ko = (uint32_t)(ks * 32);
            uint32_t Ah[4][4], Bh[2][4], Bl[2][4];
#pragma unroll
            for (int mf = 0; mf < 4; mf++)
                ldmx4(Ah[mf], st + OFF_AH + aLane + (uint32_t)(mf*16*ROWB) + ko);
#pragma unroll
            for (int g = 0; g < 2; g++)
                ldmx4(Bh[g], st + OFF_BH + bLane + (uint32_t)(g*16*ROWB) + ko);
#pragma unroll
            for (int g = 0; g < 2; g++)
                ldmx4(Bl[g], st + OFF_BL + bLane + (uint32_t)(g*16*ROWB) + ko);

#pragma unroll
            for (int mf = 0; mf < 4; mf++)
#pragma unroll
                for (int nf = 0; nf < 4; nf++)
                    mma16816(acc[mf][nf], Ah[mf], &Bh[nf >> 1][(nf & 1) * 2]);
#pragma unroll
            for (int mf = 0; mf < 4; mf++)
#pragma unroll
                for (int nf = 0; nf < 4; nf++)
                    mma16816(acc[mf][nf], Ah[mf], &Bl[nf >> 1][(nf & 1) * 2]);
#pragma unroll
            for (int mf = 0; mf < 4; mf++)
                ldmx4(Ah[mf], st + OFF_AL + aLane + (uint32_t)(mf*16*ROWB) + ko);
#pragma unroll
            for (int mf = 0; mf < 4; mf++)
#pragma unroll
                for (int nf = 0; nf < 4; nf++)
                    mma16816(acc[mf][nf], Ah[mf], &Bh[nf >> 1][(nf & 1) * 2]);
        }
        __syncthreads();
    }

    // ---- epilogue ----
    const int l4 = lane >> 2;
    const int l2 = (lane & 3) * 2;
    const float scale = (MODE == 0 && blockIdx.z == 0) ? QSCALE : 1.0f;
#pragma unroll
    for (int mf = 0; mf < 4; mf++) {
#pragma unroll
        for (int half = 0; half < 2; half++) {
            const int m = mbase + wm*64 + mf*16 + half*8 + l4;
#pragma unroll
            for (int nf = 0; nf < 4; nf++) {
                const int n  = nbase + wn*32 + nf*8 + l2;
                const float c0 = acc[mf][nf][half*2 + 0] * scale;
                const float c1 = acc[mf][nf][half*2 + 1] * scale;
                if (MODE == 0) {
                    const int b  = m >> 11;
                    const int lr = m & 2047;
                    const int h  = n >> 6;
                    const int dk = n & 63;
                    const size_t off = ((size_t)(b*H_ + h)*L_ + lr)*DK_ + dk;
                    __nv_bfloat16* dh = ((z == 0) ? g_Qh : (z == 1) ? g_Kh : g_Vh) + off;
                    __nv_bfloat16* dl = ((z == 0) ? g_Ql : (z == 1) ? g_Kl : g_Vl) + off;
                    const uint32_t ph = bfpack(c0, c1);
                    const float2 u = bfunpack(ph);
                    const uint32_t pl = bfpack(c0 - u.x, c1 - u.y);
                    *(uint32_t*)dh = ph;
                    *(uint32_t*)dl = pl;
                } else {
                    *(float2*)(Cout + (size_t)m * D_ + n) = make_float2(c0, c1);
                }
            }
        }
    }
}

// ---------------------------------------------------------------------------
// HMMA causal flash-attention, bf16-split, exp2 domain.
// Block = 128 queries of one (b,h); 8 warps x m16. K-tiles of 64 keys,
// cp.async double-buffered. S: 3-pass QK; P: C-frag->A-frag in registers,
// bf16 split; O: 3-pass PV with ldmatrix.trans V fragments.
// ---------------------------------------------------------------------------
#define AROW 144                       // 64 bf16 (128B) + 16B pad
#define SQ_H 0
#define SQ_L (128*AROW)                // 18432
#define SKV  (2*128*AROW)              // 36864
#define KV_STAGE (4*64*AROW)           // 36864
#define SKH 0
#define SKL (64*AROW)
#define SVH (2*64*AROW)
#define SVL (3*64*AROW)
#define ATTN_SMEM (SKV + 2*KV_STAGE)   // 110592

__global__ __launch_bounds__(256)
void attn_hmma()
{
    extern __shared__ char smem[];
    const uint32_t sb = smem_u32(smem);
    const int tid = threadIdx.x, wid = tid >> 5, lane = tid & 31;
    const int qt = blockIdx.x;         // 0..15
    const int bh = blockIdx.y;         // 0..63

    const size_t hbase = (size_t)bh * L_ * DK_;
    const __nv_bfloat16* Qhp = g_Qh + hbase + (size_t)qt*128*DK_;
    const __nv_bfloat16* Qlp = g_Ql + hbase + (size_t)qt*128*DK_;
    const __nv_bfloat16* Khp = g_Kh + hbase;
    const __nv_bfloat16* Klp = g_Kl + hbase;
    const __nv_bfloat16* Vhp = g_Vh + hbase;
    const __nv_bfloat16* Vlp = g_Vl + hbase;

    const int kbmax = 2*qt + 1;
    const int grow = tid >> 3;         // 0..31
    const int gc   = tid & 7;

    auto issue_kv = [&](int kb) {
        const uint32_t st = sb + SKV + (uint32_t)(kb & 1) * KV_STAGE;
        const size_t koff = (size_t)kb * 64 * DK_;
#pragma unroll
        for (int i = 0; i < 2; i++) {
            const int row = grow + i*32;
            const uint32_t d = (uint32_t)(row*AROW + gc*16);
            const size_t s = koff + (size_t)row*DK_ + gc*8;
            cpa16(st + SKH + d, Khp + s);
            cpa16(st + SKL + d, Klp + s);
            cpa16(st + SVH + d, Vhp + s);
            cpa16(st + SVL + d, Vlp + s);
        }
        asm volatile("cp.async.commit_group;" ::: "memory");
    };

    // group 0: Q (128 rows, hi+lo) + KV tile 0
    {
#pragma unroll
        for (int i = 0; i < 4; i++) {
            const int row = grow + i*32;
            const uint32_t d = (uint32_t)(row*AROW + gc*16);
            const size_t s = (size_t)row*DK_ + gc*8;
            cpa16(sb + SQ_H + d, Qhp + s);
            cpa16(sb + SQ_L + d, Qlp + s);
        }
        const uint32_t st = sb + SKV;
#pragma unroll
        for (int i = 0; i < 2; i++) {
            const int row = grow + i*32;
            const uint32_t d = (uint32_t)(row*AROW + gc*16);
            const size_t s = (size_t)row*DK_ + gc*8;
            cpa16(st + SKH + d, Khp + s);
            cpa16(st + SKL + d, Klp + s);
            cpa16(st + SVH + d, Vhp + s);
            cpa16(st + SVL + d, Vlp + s);
        }
        asm volatile("cp.async.commit_group;" ::: "memory");
    }

    const int t = lane >> 3, ri = lane & 7;
    const uint32_t aLane  = (uint32_t)((16*wid + (t&1)*8 + ri)*AROW + (t>>1)*16);
    const uint32_t bLaneK = (uint32_t)(((t>>1)*8 + ri)*AROW + (t&1)*16);
    const uint32_t vLane  = (uint32_t)((lane & 15)*AROW + (lane >> 4)*16);

    uint32_t Qha[4][4], Qla[4][4];
    float oacc[8][4];
#pragma unroll
    for (int j = 0; j < 8; j++)
#pragma unroll
        for (int q = 0; q < 4; q++) oacc[j][q] = 0.f;
    float m0 = -1e30f, m1 = -1e30f, l0 = 0.f, l1 = 0.f;

    for (int kb = 0; kb <= kbmax; kb++) {
        if (kb < kbmax) {
            issue_kv(kb + 1);
            asm volatile("cp.async.wait_group 1;" ::: "memory");
        } else {
            asm volatile("cp.async.wait_group 0;" ::: "memory");
        }
        __syncthreads();

        if (kb == 0) {
#pragma unroll
            for (int ks = 0; ks < 4; ks++) {
                ldmx4(Qha[ks], sb + SQ_H + aLane + (uint32_t)(ks*32));
                ldmx4(Qla[ks], sb + SQ_L + aLane + (uint32_t)(ks*32));
            }
        }

        const uint32_t st = sb + SKV + (uint32_t)(kb & 1) * KV_STAGE;
        const bool act = (64*kb) <= (128*qt + 16*wid + 15);
        if (act) {
            // ---- S = Q K^T (3-pass, log2 domain — Q pre-scaled) ----
            float sacc[8][4];
#pragma unroll
            for (int j = 0; j < 8; j++)
#pragma unroll
                for (int q = 0; q < 4; q++) sacc[j][q] = 0.f;

#pragma unroll
            for (int ks = 0; ks < 4; ks++) {
                uint32_t KhF[4][4], KlF[4][4];
#pragma unroll
                for (int g = 0; g < 4; g++) {
                    ldmx4(KhF[g], st + SKH + bLaneK + (uint32_t)(g*16*AROW + ks*32));
                    ldmx4(KlF[g], st + SKL + bLaneK + (uint32_t)(g*16*AROW + ks*32));
                }
#pragma unroll
                for (int j = 0; j < 8; j++) mma16816(sacc[j], Qha[ks], &KhF[j>>1][(j&1)*2]);
#pragma unroll
                for (int j = 0; j < 8; j++) mma16816(sacc[j], Qla[ks], &KhF[j>>1][(j&1)*2]);
#pragma unroll
                for (int j = 0; j < 8; j++) mma16816(sacc[j], Qha[ks], &KlF[j>>1][(j&1)*2]);
            }

            // ---- causal mask (diagonal tiles only) ----
            if (kb >= 2*qt) {
                const int q0 = 128*qt + 16*wid + (lane >> 2);
#pragma unroll
                for (int j = 0; j < 8; j++) {
                    const int key = 64*kb + 8*j + (lane & 3)*2;
                    if (key     > q0    ) sacc[j][0] = -1e30f;
                    if (key + 1 > q0    ) sacc[j][1] = -1e30f;
                    if (key     > q0 + 8) sacc[j][2] = -1e30f;
                    if (key + 1 > q0 + 8) sacc[j][3] = -1e30f;
                }
            }

            // ---- online softmax (exp2) ----
            float mx0 = sacc[0][0], mx1 = sacc[0][2];
#pragma unroll
            for (int j = 0; j < 8; j++) {
                mx0 = fmaxf(mx0, fmaxf(sacc[j][0], sacc[j][1]));
                mx1 = fmaxf(mx1, fmaxf(sacc[j][2], sacc[j][3]));
            }
            mx0 = fmaxf(mx0, __shfl_xor_sync(0xffffffffu, mx0, 1));
            mx0 = fmaxf(mx0, __shfl_xor_sync(0xffffffffu, mx0, 2));
            mx1 = fmaxf(mx1, __shfl_xor_sync(0xffffffffu, mx1, 1));
            mx1 = fmaxf(mx1, __shfl_xor_sync(0xffffffffu, mx1, 2));
            const float mn0 = fmaxf(m0, mx0), mn1 = fmaxf(m1, mx1);
            const float f0 = exp2f(m0 - mn0), f1 = exp2f(m1 - mn1);
            m0 = mn0; m1 = mn1;
            float s0 = 0.f, s1 = 0.f;
#pragma unroll
            for (int j = 0; j < 8; j++) {
                sacc[j][0] = exp2f(sacc[j][0] - mn0);
                sacc[j][1] = exp2f(sacc[j][1] - mn0);
                sacc[j][2] = exp2f(sacc[j][2] - mn1);
                sacc[j][3] = exp2f(sacc[j][3] - mn1);
                s0 += sacc[j][0] + sacc[j][1];
                s1 += sacc[j][2] + sacc[j][3];
            }
            s0 += __shfl_xor_sync(0xffffffffu, s0, 1);
            s0 += __shfl_xor_sync(0xffffffffu, s0, 2);
            s1 += __shfl_xor_sync(0xffffffffu, s1, 1);
            s1 += __shfl_xor_sync(0xffffffffu, s1, 2);
            l0 = l0*f0 + s0; l1 = l1*f1 + s1;
#pragma unroll
            for (int j = 0; j < 8; j++) {
                oacc[j][0] *= f0; oacc[j][1] *= f0;
                oacc[j][2] *= f1; oacc[j][3] *= f1;
            }

            // ---- P: C-frag -> A-frag in registers, bf16 split ----
            uint32_t pah[4][4], pal[4][4];
#pragma unroll
            for (int c = 0; c < 4; c++) {
                const int j0 = 2*c, j1 = 2*c + 1;
                pah[c][0] = bfpack(sacc[j0][0], sacc[j0][1]);
                pah[c][1] = bfpack(sacc[j0][2], sacc[j0][3]);
                pah[c][2] = bfpack(sacc[j1][0], sacc[j1][1]);
                pah[c][3] = bfpack(sacc[j1][2], sacc[j1][3]);
                float2 u;
                u = bfunpack(pah[c][0]); pal[c][0] = bfpack(sacc[j0][0]-u.x, sacc[j0][1]-u.y);
                u = bfunpack(pah[c][1]); pal[c][1] = bfpack(sacc[j0][2]-u.x, sacc[j0][3]-u.y);
                u = bfunpack(pah[c][2]); pal[c][2] = bfpack(sacc[j1][0]-u.x, sacc[j1][1]-u.y);
                u = bfunpack(pah[c][3]); pal[c][3] = bfpack(sacc[j1][2]-u.x, sacc[j1][3]-u.y);
            }

            // ---- O += P V (3-pass, V via ldmatrix.trans) ----
#pragma unroll
            for (int ks = 0; ks < 4; ks++) {
                uint32_t VhF[4][4], VlF[4][4];
#pragma unroll
                for (int g = 0; g < 4; g++) {
                    ldmx4t(VhF[g], st + SVH + vLane + (uint32_t)(ks*16*AROW + g*32));
                    ldmx4t(VlF[g], st + SVL + vLane + (uint32_t)(ks*16*AROW + g*32));
                }
#pragma unroll
                for (int j = 0; j < 8; j++) mma16816(oacc[j], pah[ks], &VhF[j>>1][(j&1)*2]);
#pragma unroll
                for (int j = 0; j < 8; j++) mma16816(oacc[j], pal[ks], &VhF[j>>1][(j&1)*2]);
#pragma unroll
                for (int j = 0; j < 8; j++) mma16816(oacc[j], pah[ks], &VlF[j>>1][(j&1)*2]);
            }
        }
        __syncthreads();
    }

    // ---- epilogue: normalize + bf16 split store to g_aoh/g_aol [B,L,D] ----
    const int b = bh >> 4, h = bh & 15;
    const float i0 = 1.f / l0, i1 = 1.f / l1;
    const int q0 = qt*128 + 16*wid + (lane >> 2);
#pragma unroll
    for (int j = 0; j < 8; j++) {
        const int col = h*64 + 8*j + (lane & 3)*2;
        {
            const float v0 = oacc[j][0]*i0, v1 = oacc[j][1]*i0;
            const uint32_t ph = bfpack(v0, v1);
            const float2 u = bfunpack(ph);
            const uint32_t pl = bfpack(v0 - u.x, v1 - u.y);
            const size_t o = ((size_t)(b*L_ + q0))*D_ + col;
            *(uint32_t*)(g_aoh + o) = ph;
            *(uint32_t*)(g_aol + o) = pl;
        }
        {
            const float v0 = oacc[j][2]*i1, v1 = oacc[j][3]*i1;
            const uint32_t ph = bfpack(v0, v1);
            const float2 u = bfunpack(ph);
            const uint32_t pl = bfpack(v0 - u.x, v1 - u.y);
            const size_t o = ((size_t)(b*L_ + q0 + 8))*D_ + col;
            *(uint32_t*)(g_aoh + o) = ph;
            *(uint32_t*)(g_aol + o) = pl;
        }
    }
}

// ---------------------------------------------------------------------------
extern "C" void kernel_launch(void* const* d_in, const int* in_sizes, int n_in,
                              void* d_out, int out_size)
{
    const float* x  = (const float*)d_in[0];
    const float* Wq = (const float*)d_in[1];
    const float* Wk = (const float*)d_in[2];
    const float* Wv = (const float*)d_in[3];
    const float* Wo = (const float*)d_in[4];
    float* out = (float*)d_out;

    cudaFuncSetAttribute(gemm_hmma<0>,
                         cudaFuncAttributeMaxDynamicSharedMemorySize, GEMM_SMEM);
    cudaFuncSetAttribute(gemm_hmma<1>,
                         cudaFuncAttributeMaxDynamicSharedMemorySize, GEMM_SMEM);
    cudaFuncSetAttribute(attn_hmma,
                         cudaFuncAttributeMaxDynamicSharedMemorySize, ATTN_SMEM);

    const int n4x = (B_*L_*D_) / 4;
    const int n4w = (D_*D_) / 4;

    split_kernel<<<(n4x + 255)/256, 256>>>(x,  0, n4x);
    split_kernel<<<(n4w + 255)/256, 256>>>(Wq, 1, n4w);
    split_kernel<<<(n4w + 255)/256, 256>>>(Wk, 2, n4w);
    split_kernel<<<(n4w + 255)/256, 256>>>(Wv, 3, n4w);
    split_kernel<<<(n4w + 255)/256, 256>>>(Wo, 4, n4w);

    // Q/K/V projections -> bf16 split (Q pre-scaled into exp2 domain)
    gemm_hmma<0><<<dim3(64, 8, 3), 256, GEMM_SMEM>>>(nullptr);

    // HMMA causal flash-attention -> bf16 split AO
    attn_hmma<<<dim3(16, 64), 256, ATTN_SMEM>>>();

    // O-projection -> fp32 out
    gemm_hmma<1><<<dim3(64, 8, 1), 256, GEMM_SMEM>>>(out);
}

// round 8
// speedup vs baseline: 3.3785x; 1.4504x over previous
#include <cuda_runtime.h>
#include <cuda_fp16.h>
#include <cstdint>

#define B_  4
#define L_  2048
#define D_  1024
#define H_  16
#define DK_ 64

// ---------------------------------------------------------------------------
// Scratch (static __device__ — no allocation allowed)
// f16 2-pass scheme: A-side operands keep hi+lo, B-side operands hi only.
// ---------------------------------------------------------------------------
__device__ __half g_xh [B_*L_*D_];
__device__ __half g_xl [B_*L_*D_];
__device__ __half g_Wh [4*D_*D_];      // Wq,Wk,Wv,Wo hi only
__device__ __half g_aoh[B_*L_*D_];
__device__ __half g_aol[B_*L_*D_];
__device__ __half g_Qh[B_*H_*L_*DK_];  // Q hi+lo (A-side of S)
__device__ __half g_Ql[B_*H_*L_*DK_];
__device__ __half g_Kh[B_*H_*L_*DK_];  // K hi only (B-side of S)
__device__ __half g_Vh[B_*H_*L_*DK_];  // V hi only (B-side of PV)

// ---------------------------------------------------------------------------
// PTX helpers (compute_100-safe)
// ---------------------------------------------------------------------------
__device__ __forceinline__ uint32_t smem_u32(const void* p) {
    uint32_t a;
    asm("{ .reg .u64 t; cvta.to.shared.u64 t, %1; cvt.u32.u64 %0, t; }"
        : "=r"(a) : "l"(p));
    return a;
}
__device__ __forceinline__ void ldmx4(uint32_t* r, uint32_t a) {
    asm volatile("ldmatrix.sync.aligned.m8n8.x4.shared.b16 {%0,%1,%2,%3}, [%4];"
                 : "=r"(r[0]), "=r"(r[1]), "=r"(r[2]), "=r"(r[3]) : "r"(a));
}
__device__ __forceinline__ void ldmx4t(uint32_t* r, uint32_t a) {
    asm volatile("ldmatrix.sync.aligned.m8n8.x4.trans.shared.b16 {%0,%1,%2,%3}, [%4];"
                 : "=r"(r[0]), "=r"(r[1]), "=r"(r[2]), "=r"(r[3]) : "r"(a));
}
__device__ __forceinline__ void mma16816(float* c, const uint32_t* a, const uint32_t* b) {
    asm volatile("mma.sync.aligned.m16n8k16.row.col.f32.f16.f16.f32 "
                 "{%0,%1,%2,%3}, {%4,%5,%6,%7}, {%8,%9}, {%0,%1,%2,%3};"
                 : "+f"(c[0]), "+f"(c[1]), "+f"(c[2]), "+f"(c[3])
                 : "r"(a[0]), "r"(a[1]), "r"(a[2]), "r"(a[3]),
                   "r"(b[0]), "r"(b[1]));
}
__device__ __forceinline__ void cpa16(uint32_t s, const void* g) {
    asm volatile("cp.async.cg.shared.global [%0], [%1], 16;"
                 :: "r"(s), "l"(__cvta_generic_to_global(g)));
}
// pack two fp32 -> f16x2 (lo arg in low half)
__device__ __forceinline__ uint32_t hfpack(float lo, float hi) {
    uint32_t d;
    asm("cvt.rn.f16x2.f32 %0, %1, %2;" : "=r"(d) : "f"(hi), "f"(lo));
    return d;
}
__device__ __forceinline__ float2 hfunpack(uint32_t u) {
    __half2 t = *reinterpret_cast<__half2*>(&u);
    return make_float2(__half2float(t.x), __half2float(t.y));
}

// ---------------------------------------------------------------------------
// f16 split of inputs: sel 0 = x (hi+lo), sel 1..4 = Wq/Wk/Wv/Wo (hi only)
// ---------------------------------------------------------------------------
__global__ void split_kernel(const float* __restrict__ src, int sel, int n4)
{
    int i = blockIdx.x * blockDim.x + threadIdx.x;
    if (i >= n4) return;
    float4 v = ((const float4*)src)[i];
    __half h0 = __float2half(v.x);
    __half h1 = __float2half(v.y);
    __half h2 = __float2half(v.z);
    __half h3 = __float2half(v.w);
    if (sel == 0) {
        ((__half2*)g_xh)[2*i]   = __halves2half2(h0, h1);
        ((__half2*)g_xh)[2*i+1] = __halves2half2(h2, h3);
        __half l0 = __float2half(v.x - __half2float(h0));
        __half l1 = __float2half(v.y - __half2float(h1));
        __half l2 = __float2half(v.z - __half2float(h2));
        __half l3 = __float2half(v.w - __half2float(h3));
        ((__half2*)g_xl)[2*i]   = __halves2half2(l0, l1);
        ((__half2*)g_xl)[2*i+1] = __halves2half2(l2, l3);
    } else {
        __half* hi = g_Wh + (size_t)(sel-1)*D_*D_;
        ((__half2*)hi)[2*i]   = __halves2half2(h0, h1);
        ((__half2*)hi)[2*i+1] = __halves2half2(h2, h3);
    }
}

// ---------------------------------------------------------------------------
// HMMA f16 2-pass GEMM:  C[m,n] = sum_k (Ah+Al)[m,k] * Wh[n,k]
// CTA 128x128, K-tile 32, 3-stage cp.async pipeline, one barrier per tile.
// 8 warps, warp tile 64x32. Per k16: 10 ldmatrix + 32 mma.
// MODE 0: A = x(hi/lo); z=0 -> Qh+Ql (scaled 0.125*log2e), z=1 -> Kh, z=2 -> Vh
// MODE 1: A = AO(hi/lo), W = Wo; fp32 row-major Cout.
// ---------------------------------------------------------------------------
#define ROWB    80
#define G_AH    0
#define G_AL    (128*ROWB)             // 10240
#define G_BH    (2*128*ROWB)           // 20480
#define G_STAGE (3*128*ROWB)           // 30720
#define GEMM_SMEM (3*G_STAGE)          // 92160

#define QSCALE 0.18033688011112042f    // 0.125 * log2(e)

template<int MODE>
__global__ __launch_bounds__(256)
void gemm_hmma(float* __restrict__ Cout)
{
    extern __shared__ char smem[];
    const uint32_t sb = smem_u32(smem);
    const int tid  = threadIdx.x;
    const int wid  = tid >> 5;
    const int lane = tid & 31;
    const int bm   = blockIdx.x;
    const int bn   = blockIdx.y;
    const int z    = (MODE == 0) ? blockIdx.z : 3;

    const __half* Agh = (MODE == 0) ? g_xh : g_aoh;
    const __half* Agl = (MODE == 0) ? g_xl : g_aol;
    const __half* Wgh = g_Wh + (size_t)z * D_ * D_;

    const int mbase = bm * 128;
    const int nbase = bn * 128;
    const int wm = wid >> 2;
    const int wn = wid & 3;

    const int t  = lane >> 3;
    const int ri = lane & 7;
    const uint32_t aLane = (uint32_t)((wm*64 + (t&1)*8 + ri) * ROWB + (t>>1)*16);
    const uint32_t bLane = (uint32_t)((wn*32 + (t>>1)*8 + ri) * ROWB + (t&1)*16);

    const int grow0 = tid >> 2;
    const int gc    = (tid & 3);
    const uint32_t so0 = (uint32_t)(grow0 * ROWB + gc * 16);
    const uint32_t so1 = so0 + 64u * ROWB;

    float acc[4][4][4];
#pragma unroll
    for (int i = 0; i < 4; i++)
#pragma unroll
        for (int j = 0; j < 4; j++)
#pragma unroll
            for (int q = 0; q < 4; q++) acc[i][j][q] = 0.f;

    const int NT = D_ / 32;            // 32

    auto issue_stage = [&](int kt) {
        const uint32_t st = sb + (uint32_t)(kt % 3) * G_STAGE;
        const int kcol = kt * 32;
        const size_t ga0 = (size_t)(mbase + grow0) * D_ + kcol + gc * 8;
        const size_t ga1 = ga0 + (size_t)64 * D_;
        const size_t gb0 = (size_t)(nbase + grow0) * D_ + kcol + gc * 8;
        const size_t gb1 = gb0 + (size_t)64 * D_;
        cpa16(st + G_AH + so0, Agh + ga0);
        cpa16(st + G_AH + so1, Agh + ga1);
        cpa16(st + G_AL + so0, Agl + ga0);
        cpa16(st + G_AL + so1, Agl + ga1);
        cpa16(st + G_BH + so0, Wgh + gb0);
        cpa16(st + G_BH + so1, Wgh + gb1);
        asm volatile("cp.async.commit_group;" ::: "memory");
    };

    issue_stage(0);
    issue_stage(1);

    for (int kt = 0; kt < NT; kt++) {
        if (kt == NT - 1) { asm volatile("cp.async.wait_group 0;" ::: "memory"); }
        else              { asm volatile("cp.async.wait_group 1;" ::: "memory"); }
        __syncthreads();                        // stage kt visible; stage kt-1 free
        if (kt + 2 < NT) issue_stage(kt + 2);   // writes buffer (kt-1)%3

        const uint32_t st = sb + (uint32_t)(kt % 3) * G_STAGE;
#pragma unroll
        for (int ks = 0; ks < 2; ks++) {
            const uint32_t ko = (uint32_t)(ks * 32);
            uint32_t Ah[4][4], Al[4][4], Bh[2][4];
#pragma unroll
            for (int mf = 0; mf < 4; mf++)
                ldmx4(Ah[mf], st + G_AH + aLane + (uint32_t)(mf*16*ROWB) + ko);
#pragma unroll
            for (int g = 0; g < 2; g++)
                ldmx4(Bh[g], st + G_BH + bLane + (uint32_t)(g*16*ROWB) + ko);
#pragma unroll
            for (int mf = 0; mf < 4; mf++)
                ldmx4(Al[mf], st + G_AL + aLane + (uint32_t)(mf*16*ROWB) + ko);

#pragma unroll
            for (int mf = 0; mf < 4; mf++)
#pragma unroll
                for (int nf = 0; nf < 4; nf++)
                    mma16816(acc[mf][nf], Ah[mf], &Bh[nf >> 1][(nf & 1) * 2]);
#pragma unroll
            for (int mf = 0; mf < 4; mf++)
#pragma unroll
                for (int nf = 0; nf < 4; nf++)
                    mma16816(acc[mf][nf], Al[mf], &Bh[nf >> 1][(nf & 1) * 2]);
        }
    }
    __syncthreads();

    // ---- epilogue ----
    const int l4 = lane >> 2;
    const int l2 = (lane & 3) * 2;
    const float scale = (MODE == 0 && blockIdx.z == 0) ? QSCALE : 1.0f;
#pragma unroll
    for (int mf = 0; mf < 4; mf++) {
#pragma unroll
        for (int half = 0; half < 2; half++) {
            const int m = mbase + wm*64 + mf*16 + half*8 + l4;
#pragma unroll
            for (int nf = 0; nf < 4; nf++) {
                const int n  = nbase + wn*32 + nf*8 + l2;
                const float c0 = acc[mf][nf][half*2 + 0] * scale;
                const float c1 = acc[mf][nf][half*2 + 1] * scale;
                if (MODE == 0) {
                    const int b  = m >> 11;
                    const int lr = m & 2047;
                    const int h  = n >> 6;
                    const int dk = n & 63;
                    const size_t off = ((size_t)(b*H_ + h)*L_ + lr)*DK_ + dk;
                    const uint32_t ph = hfpack(c0, c1);
                    if (z == 0) {
                        const float2 u = hfunpack(ph);
                        *(uint32_t*)(g_Qh + off) = ph;
                        *(uint32_t*)(g_Ql + off) = hfpack(c0 - u.x, c1 - u.y);
                    } else if (z == 1) {
                        *(uint32_t*)(g_Kh + off) = ph;
                    } else {
                        *(uint32_t*)(g_Vh + off) = ph;
                    }
                } else {
                    *(float2*)(Cout + (size_t)m * D_ + n) = make_float2(c0, c1);
                }
            }
        }
    }
}

// ---------------------------------------------------------------------------
// HMMA causal flash-attention, f16 2-pass, exp2 domain.
// Block = 128 queries of one (b,h); 8 warps x m16. 64-key tiles,
// double-buffered Kh/Vh. S = QhKh + QlKh; P split in regs; O = PhVh + PlVh.
// qt reversed so heavy tiles launch first.
// ---------------------------------------------------------------------------
#define AROW 144
#define SQ_H 0
#define SQ_L (128*AROW)                // 18432
#define SKV  (2*128*AROW)              // 36864
#define A_KH 0
#define A_VH (64*AROW)                 // 9216
#define KV_STAGE (2*64*AROW)           // 18432
#define ATTN_SMEM (SKV + 2*KV_STAGE)   // 73728

__global__ __launch_bounds__(256)
void attn_hmma()
{
    extern __shared__ char smem[];
    const uint32_t sb = smem_u32(smem);
    const int tid = threadIdx.x, wid = tid >> 5, lane = tid & 31;
    const int qt = (int)gridDim.x - 1 - (int)blockIdx.x;   // heavy first
    const int bh = blockIdx.y;

    const size_t hbase = (size_t)bh * L_ * DK_;
    const __half* Qhp = g_Qh + hbase + (size_t)qt*128*DK_;
    const __half* Qlp = g_Ql + hbase + (size_t)qt*128*DK_;
    const __half* Khp = g_Kh + hbase;
    const __half* Vhp = g_Vh + hbase;

    const int kbmax = 2*qt + 1;
    const int grow = tid >> 3;
    const int gc   = tid & 7;

    auto issue_kv = [&](int kb) {
        const uint32_t st = sb + SKV + (uint32_t)(kb & 1) * KV_STAGE;
        const size_t koff = (size_t)kb * 64 * DK_;
#pragma unroll
        for (int i = 0; i < 2; i++) {
            const int row = grow + i*32;
            const uint32_t d = (uint32_t)(row*AROW + gc*16);
            const size_t s = koff + (size_t)row*DK_ + gc*8;
            cpa16(st + A_KH + d, Khp + s);
            cpa16(st + A_VH + d, Vhp + s);
        }
        asm volatile("cp.async.commit_group;" ::: "memory");
    };

    {   // group 0: Q hi+lo + KV tile 0
#pragma unroll
        for (int i = 0; i < 4; i++) {
            const int row = grow + i*32;
            const uint32_t d = (uint32_t)(row*AROW + gc*16);
            const size_t s = (size_t)row*DK_ + gc*8;
            cpa16(sb + SQ_H + d, Qhp + s);
            cpa16(sb + SQ_L + d, Qlp + s);
        }
        const uint32_t st = sb + SKV;
#pragma unroll
        for (int i = 0; i < 2; i++) {
            const int row = grow + i*32;
            const uint32_t d = (uint32_t)(row*AROW + gc*16);
            const size_t s = (size_t)row*DK_ + gc*8;
            cpa16(st + A_KH + d, Khp + s);
            cpa16(st + A_VH + d, Vhp + s);
        }
        asm volatile("cp.async.commit_group;" ::: "memory");
    }

    const int t = lane >> 3, ri = lane & 7;
    const uint32_t aLane  = (uint32_t)((16*wid + (t&1)*8 + ri)*AROW + (t>>1)*16);
    const uint32_t bLaneK = (uint32_t)(((t>>1)*8 + ri)*AROW + (t&1)*16);
    const uint32_t vLane  = (uint32_t)((lane & 15)*AROW + (lane >> 4)*16);

    uint32_t Qha[4][4], Qla[4][4];
    float oacc[8][4];
#pragma unroll
    for (int j = 0; j < 8; j++)
#pragma unroll
        for (int q = 0; q < 4; q++) oacc[j][q] = 0.f;
    float m0 = -1e30f, m1 = -1e30f, l0 = 0.f, l1 = 0.f;

    for (int kb = 0; kb <= kbmax; kb++) {
        if (kb < kbmax) {
            issue_kv(kb + 1);
            asm volatile("cp.async.wait_group 1;" ::: "memory");
        } else {
            asm volatile("cp.async.wait_group 0;" ::: "memory");
        }
        __syncthreads();

        if (kb == 0) {
#pragma unroll
            for (int ks = 0; ks < 4; ks++) {
                ldmx4(Qha[ks], sb + SQ_H + aLane + (uint32_t)(ks*32));
                ldmx4(Qla[ks], sb + SQ_L + aLane + (uint32_t)(ks*32));
            }
        }

        const uint32_t st = sb + SKV + (uint32_t)(kb & 1) * KV_STAGE;
        const bool act = (64*kb) <= (128*qt + 16*wid + 15);
        if (act) {
            // ---- S = Q K^T (2-pass, exp2 domain) ----
            float sacc[8][4];
#pragma unroll
            for (int j = 0; j < 8; j++)
#pragma unroll
                for (int q = 0; q < 4; q++) sacc[j][q] = 0.f;

#pragma unroll
            for (int ks = 0; ks < 4; ks++) {
                uint32_t KhF[4][4];
#pragma unroll
                for (int g = 0; g < 4; g++)
                    ldmx4(KhF[g], st + A_KH + bLaneK + (uint32_t)(g*16*AROW + ks*32));
#pragma unroll
                for (int j = 0; j < 8; j++) mma16816(sacc[j], Qha[ks], &KhF[j>>1][(j&1)*2]);
#pragma unroll
                for (int j = 0; j < 8; j++) mma16816(sacc[j], Qla[ks], &KhF[j>>1][(j&1)*2]);
            }

            // ---- causal mask (diagonal tiles only) ----
            if (kb >= 2*qt) {
                const int q0 = 128*qt + 16*wid + (lane >> 2);
#pragma unroll
                for (int j = 0; j < 8; j++) {
                    const int key = 64*kb + 8*j + (lane & 3)*2;
                    if (key     > q0    ) sacc[j][0] = -1e30f;
                    if (key + 1 > q0    ) sacc[j][1] = -1e30f;
                    if (key     > q0 + 8) sacc[j][2] = -1e30f;
                    if (key + 1 > q0 + 8) sacc[j][3] = -1e30f;
                }
            }

            // ---- online softmax (exp2) ----
            float mx0 = sacc[0][0], mx1 = sacc[0][2];
#pragma unroll
            for (int j = 0; j < 8; j++) {
                mx0 = fmaxf(mx0, fmaxf(sacc[j][0], sacc[j][1]));
                mx1 = fmaxf(mx1, fmaxf(sacc[j][2], sacc[j][3]));
            }
            mx0 = fmaxf(mx0, __shfl_xor_sync(0xffffffffu, mx0, 1));
            mx0 = fmaxf(mx0, __shfl_xor_sync(0xffffffffu, mx0, 2));
            mx1 = fmaxf(mx1, __shfl_xor_sync(0xffffffffu, mx1, 1));
            mx1 = fmaxf(mx1, __shfl_xor_sync(0xffffffffu, mx1, 2));
            const float mn0 = fmaxf(m0, mx0), mn1 = fmaxf(m1, mx1);
            const float f0 = exp2f(m0 - mn0), f1 = exp2f(m1 - mn1);
            m0 = mn0; m1 = mn1;
            float s0 = 0.f, s1 = 0.f;
#pragma unroll
            for (int j = 0; j < 8; j++) {
                sacc[j][0] = exp2f(sacc[j][0] - mn0);
                sacc[j][1] = exp2f(sacc[j][1] - mn0);
                sacc[j][2] = exp2f(sacc[j][2] - mn1);
                sacc[j][3] = exp2f(sacc[j][3] - mn1);
                s0 += sacc[j][0] + sacc[j][1];
                s1 += sacc[j][2] + sacc[j][3];
            }
            s0 += __shfl_xor_sync(0xffffffffu, s0, 1);
            s0 += __shfl_xor_sync(0xffffffffu, s0, 2);
            s1 += __shfl_xor_sync(0xffffffffu, s1, 1);
            s1 += __shfl_xor_sync(0xffffffffu, s1, 2);
            l0 = l0*f0 + s0; l1 = l1*f1 + s1;
#pragma unroll
            for (int j = 0; j < 8; j++) {
                oacc[j][0] *= f0; oacc[j][1] *= f0;
                oacc[j][2] *= f1; oacc[j][3] *= f1;
            }

            // ---- P: C-frag -> A-frag in registers, f16 split ----
            uint32_t pah[4][4], pal[4][4];
#pragma unroll
            for (int c = 0; c < 4; c++) {
                const int j0 = 2*c, j1 = 2*c + 1;
                pah[c][0] = hfpack(sacc[j0][0], sacc[j0][1]);
                pah[c][1] = hfpack(sacc[j0][2], sacc[j0][3]);
                pah[c][2] = hfpack(sacc[j1][0], sacc[j1][1]);
                pah[c][3] = hfpack(sacc[j1][2], sacc[j1][3]);
                float2 u;
                u = hfunpack(pah[c][0]); pal[c][0] = hfpack(sacc[j0][0]-u.x, sacc[j0][1]-u.y);
                u = hfunpack(pah[c][1]); pal[c][1] = hfpack(sacc[j0][2]-u.x, sacc[j0][3]-u.y);
                u = hfunpack(pah[c][2]); pal[c][2] = hfpack(sacc[j1][0]-u.x, sacc[j1][1]-u.y);
                u = hfunpack(pah[c][3]); pal[c][3] = hfpack(sacc[j1][2]-u.x, sacc[j1][3]-u.y);
            }

            // ---- O += P V (2-pass, V via ldmatrix.trans) ----
#pragma unroll
            for (int ks = 0; ks < 4; ks++) {
                uint32_t VhF[4][4];
#pragma unroll
                for (int g = 0; g < 4; g++)
                    ldmx4t(VhF[g], st + A_VH + vLane + (uint32_t)(ks*16*AROW + g*32));
#pragma unroll
                for (int j = 0; j < 8; j++) mma16816(oacc[j], pah[ks], &VhF[j>>1][(j&1)*2]);
#pragma unroll
                for (int j = 0; j < 8; j++) mma16816(oacc[j], pal[ks], &VhF[j>>1][(j&1)*2]);
            }
        }
        __syncthreads();
    }

    // ---- epilogue: normalize + f16 split store to g_aoh/g_aol [B,L,D] ----
    const int b = bh >> 4, h = bh & 15;
    const float i0 = 1.f / l0, i1 = 1.f / l1;
    const int q0 = qt*128 + 16*wid + (lane >> 2);
#pragma unroll
    for (int j = 0; j < 8; j++) {
        const int col = h*64 + 8*j + (lane & 3)*2;
        {
            const float v0 = oacc[j][0]*i0, v1 = oacc[j][1]*i0;
            const uint32_t ph = hfpack(v0, v1);
            const float2 u = hfunpack(ph);
            const uint32_t pl = hfpack(v0 - u.x, v1 - u.y);
            const size_t o = ((size_t)(b*L_ + q0))*D_ + col;
            *(uint32_t*)(g_aoh + o) = ph;
            *(uint32_t*)(g_aol + o) = pl;
        }
        {
            const float v0 = oacc[j][2]*i1, v1 = oacc[j][3]*i1;
            const uint32_t ph = hfpack(v0, v1);
            const float2 u = hfunpack(ph);
            const uint32_t pl = hfpack(v0 - u.x, v1 - u.y);
            const size_t o = ((size_t)(b*L_ + q0 + 8))*D_ + col;
            *(uint32_t*)(g_aoh + o) = ph;
            *(uint32_t*)(g_aol + o) = pl;
        }
    }
}

// ---------------------------------------------------------------------------
extern "C" void kernel_launch(void* const* d_in, const int* in_sizes, int n_in,
                              void* d_out, int out_size)
{
    const float* x  = (const float*)d_in[0];
    const float* Wq = (const float*)d_in[1];
    const float* Wk = (const float*)d_in[2];
    const float* Wv = (const float*)d_in[3];
    const float* Wo = (const float*)d_in[4];
    float* out = (float*)d_out;

    cudaFuncSetAttribute(gemm_hmma<0>,
                         cudaFuncAttributeMaxDynamicSharedMemorySize, GEMM_SMEM);
    cudaFuncSetAttribute(gemm_hmma<1>,
                         cudaFuncAttributeMaxDynamicSharedMemorySize, GEMM_SMEM);
    cudaFuncSetAttribute(attn_hmma,
                         cudaFuncAttributeMaxDynamicSharedMemorySize, ATTN_SMEM);

    const int n4x = (B_*L_*D_) / 4;
    const int n4w = (D_*D_) / 4;

    split_kernel<<<(n4x + 255)/256, 256>>>(x,  0, n4x);
    split_kernel<<<(n4w + 255)/256, 256>>>(Wq, 1, n4w);
    split_kernel<<<(n4w + 255)/256, 256>>>(Wk, 2, n4w);
    split_kernel<<<(n4w + 255)/256, 256>>>(Wv, 3, n4w);
    split_kernel<<<(n4w + 255)/256, 256>>>(Wo, 4, n4w);

    // Q/K/V projections (f16 2-pass; Q pre-scaled into exp2 domain)
    gemm_hmma<0><<<dim3(64, 8, 3), 256, GEMM_SMEM>>>(nullptr);

    // HMMA causal flash-attention
    attn_hmma<<<dim3(16, 64), 256, ATTN_SMEM>>>();

    // O-projection -> fp32 out
    gemm_hmma<1><<<dim3(64, 8, 1), 256, GEMM_SMEM>>>(out);
}

// round 9
// speedup vs baseline: 4.3400x; 1.2846x over previous
#include <cuda_runtime.h>
#include <cuda_fp16.h>
#include <cstdint>

#define B_  4
#define L_  2048
#define D_  1024
#define H_  16
#define DK_ 64

// ---------------------------------------------------------------------------
// Scratch (static __device__ — no allocation allowed)
// ---------------------------------------------------------------------------
__device__ __half g_xh [B_*L_*D_];
__device__ __half g_xl [B_*L_*D_];
__device__ __half g_Wh [4*D_*D_];      // Wq,Wk,Wv,Wo hi only
__device__ __half g_aoh[B_*L_*D_];
__device__ __half g_aol[B_*L_*D_];
__device__ __half g_Qh[B_*H_*L_*DK_];  // Q hi+lo (A-side of S)
__device__ __half g_Ql[B_*H_*L_*DK_];
__device__ __half g_Kh[B_*H_*L_*DK_];  // K hi only
__device__ __half g_Vh[B_*H_*L_*DK_];  // V hi only

// ---------------------------------------------------------------------------
// PTX helpers (compute_100-safe)
// ---------------------------------------------------------------------------
__device__ __forceinline__ uint32_t smem_u32(const void* p) {
    uint32_t a;
    asm("{ .reg .u64 t; cvta.to.shared.u64 t, %1; cvt.u32.u64 %0, t; }"
        : "=r"(a) : "l"(p));
    return a;
}
__device__ __forceinline__ void ldmx4(uint32_t* r, uint32_t a) {
    asm volatile("ldmatrix.sync.aligned.m8n8.x4.shared.b16 {%0,%1,%2,%3}, [%4];"
                 : "=r"(r[0]), "=r"(r[1]), "=r"(r[2]), "=r"(r[3]) : "r"(a));
}
__device__ __forceinline__ void ldmx4t(uint32_t* r, uint32_t a) {
    asm volatile("ldmatrix.sync.aligned.m8n8.x4.trans.shared.b16 {%0,%1,%2,%3}, [%4];"
                 : "=r"(r[0]), "=r"(r[1]), "=r"(r[2]), "=r"(r[3]) : "r"(a));
}
__device__ __forceinline__ void mma16816(float* c, const uint32_t* a, const uint32_t* b) {
    asm volatile("mma.sync.aligned.m16n8k16.row.col.f32.f16.f16.f32 "
                 "{%0,%1,%2,%3}, {%4,%5,%6,%7}, {%8,%9}, {%0,%1,%2,%3};"
                 : "+f"(c[0]), "+f"(c[1]), "+f"(c[2]), "+f"(c[3])
                 : "r"(a[0]), "r"(a[1]), "r"(a[2]), "r"(a[3]),
                   "r"(b[0]), "r"(b[1]));
}
__device__ __forceinline__ void cpa16(uint32_t s, const void* g) {
    asm volatile("cp.async.cg.shared.global [%0], [%1], 16;"
                 :: "r"(s), "l"(__cvta_generic_to_global(g)));
}
__device__ __forceinline__ uint32_t hfpack(float lo, float hi) {
    uint32_t d;
    asm("cvt.rn.f16x2.f32 %0, %1, %2;" : "=r"(d) : "f"(hi), "f"(lo));
    return d;
}
__device__ __forceinline__ float2 hfunpack(uint32_t u) {
    __half2 t = *reinterpret_cast<__half2*>(&u);
    return make_float2(__half2float(t.x), __half2float(t.y));
}

// ---------------------------------------------------------------------------
// x split (hi+lo)
// ---------------------------------------------------------------------------
__global__ void xsplit_kernel(const float* __restrict__ src, int n4)
{
    int i = blockIdx.x * blockDim.x + threadIdx.x;
    if (i >= n4) return;
    float4 v = ((const float4*)src)[i];
    __half h0 = __float2half(v.x);
    __half h1 = __float2half(v.y);
    __half h2 = __float2half(v.z);
    __half h3 = __float2half(v.w);
    ((__half2*)g_xh)[2*i]   = __halves2half2(h0, h1);
    ((__half2*)g_xh)[2*i+1] = __halves2half2(h2, h3);
    __half l0 = __float2half(v.x - __half2float(h0));
    __half l1 = __float2half(v.y - __half2float(h1));
    __half l2 = __float2half(v.z - __half2float(h2));
    __half l3 = __float2half(v.w - __half2float(h3));
    ((__half2*)g_xl)[2*i]   = __halves2half2(l0, l1);
    ((__half2*)g_xl)[2*i+1] = __halves2half2(l2, l3);
}

// ---------------------------------------------------------------------------
// all 4 weights -> f16 hi, one launch (n4w per weight, blocks never straddle)
// ---------------------------------------------------------------------------
__global__ void wsplit_kernel(const float* __restrict__ w0, const float* __restrict__ w1,
                              const float* __restrict__ w2, const float* __restrict__ w3,
                              int n4w)
{
    int i = blockIdx.x * blockDim.x + threadIdx.x;
    if (i >= 4*n4w) return;
    const int sel = i / n4w;
    const int j   = i - sel * n4w;
    const float* src = (sel == 0) ? w0 : (sel == 1) ? w1 : (sel == 2) ? w2 : w3;
    float4 v = ((const float4*)src)[j];
    __half2* hi = (__half2*)(g_Wh + (size_t)sel * D_ * D_);
    hi[2*j]   = __halves2half2(__float2half(v.x), __float2half(v.y));
    hi[2*j+1] = __halves2half2(__float2half(v.z), __float2half(v.w));
}

// ---------------------------------------------------------------------------
// HMMA f16 GEMM:  C[m,n] = sum_k A[m,k] * Wh[n,k]
// A = hi (+ lo pass only where precision matters: Q-proj and O-proj).
// CTA 128x128, K-tile 32, 3-stage cp.async pipeline, 8 warps (64x32 each).
// MODE 0: A=x; z=0 -> Qh+Ql (scaled 0.125*log2e, 2-pass), z=1 -> Kh (1-pass),
//         z=2 -> Vh (1-pass). MODE 1: A=AO (2-pass), W=Wo -> fp32 Cout.
// ---------------------------------------------------------------------------
#define ROWB    80
#define G_AH    0
#define G_AL    (128*ROWB)
#define G_BH    (2*128*ROWB)
#define G_STAGE (3*128*ROWB)           // 30720
#define GEMM_SMEM (3*G_STAGE)          // 92160

#define QSCALE 0.18033688011112042f    // 0.125 * log2(e)

template<int MODE>
__global__ __launch_bounds__(256)
void gemm_hmma(float* __restrict__ Cout)
{
    extern __shared__ char smem[];
    const uint32_t sb = smem_u32(smem);
    const int tid  = threadIdx.x;
    const int wid  = tid >> 5;
    const int lane = tid & 31;
    const int bm   = blockIdx.x;
    const int bn   = blockIdx.y;
    const int z    = (MODE == 0) ? blockIdx.z : 3;
    const bool useAL = (MODE == 1) || (z == 0);   // lo pass: Q-proj + O-proj only

    const __half* Agh = (MODE == 0) ? g_xh : g_aoh;
    const __half* Agl = (MODE == 0) ? g_xl : g_aol;
    const __half* Wgh = g_Wh + (size_t)z * D_ * D_;

    const int mbase = bm * 128;
    const int nbase = bn * 128;
    const int wm = wid >> 2;
    const int wn = wid & 3;

    const int t  = lane >> 3;
    const int ri = lane & 7;
    const uint32_t aLane = (uint32_t)((wm*64 + (t&1)*8 + ri) * ROWB + (t>>1)*16);
    const uint32_t bLane = (uint32_t)((wn*32 + (t>>1)*8 + ri) * ROWB + (t&1)*16);

    const int grow0 = tid >> 2;
    const int gc    = (tid & 3);
    const uint32_t so0 = (uint32_t)(grow0 * ROWB + gc * 16);
    const uint32_t so1 = so0 + 64u * ROWB;

    float acc[4][4][4];
#pragma unroll
    for (int i = 0; i < 4; i++)
#pragma unroll
        for (int j = 0; j < 4; j++)
#pragma unroll
            for (int q = 0; q < 4; q++) acc[i][j][q] = 0.f;

    const int NT = D_ / 32;

    auto issue_stage = [&](int kt) {
        const uint32_t st = sb + (uint32_t)(kt % 3) * G_STAGE;
        const int kcol = kt * 32;
        const size_t ga0 = (size_t)(mbase + grow0) * D_ + kcol + gc * 8;
        const size_t ga1 = ga0 + (size_t)64 * D_;
        const size_t gb0 = (size_t)(nbase + grow0) * D_ + kcol + gc * 8;
        const size_t gb1 = gb0 + (size_t)64 * D_;
        cpa16(st + G_AH + so0, Agh + ga0);
        cpa16(st + G_AH + so1, Agh + ga1);
        if (useAL) {
            cpa16(st + G_AL + so0, Agl + ga0);
            cpa16(st + G_AL + so1, Agl + ga1);
        }
        cpa16(st + G_BH + so0, Wgh + gb0);
        cpa16(st + G_BH + so1, Wgh + gb1);
        asm volatile("cp.async.commit_group;" ::: "memory");
    };

    issue_stage(0);
    issue_stage(1);

    for (int kt = 0; kt < NT; kt++) {
        if (kt == NT - 1) { asm volatile("cp.async.wait_group 0;" ::: "memory"); }
        else              { asm volatile("cp.async.wait_group 1;" ::: "memory"); }
        __syncthreads();
        if (kt + 2 < NT) issue_stage(kt + 2);

        const uint32_t st = sb + (uint32_t)(kt % 3) * G_STAGE;
#pragma unroll
        for (int ks = 0; ks < 2; ks++) {
            const uint32_t ko = (uint32_t)(ks * 32);
            uint32_t Ah[4][4], Bh[2][4];
#pragma unroll
            for (int mf = 0; mf < 4; mf++)
                ldmx4(Ah[mf], st + G_AH + aLane + (uint32_t)(mf*16*ROWB) + ko);
#pragma unroll
            for (int g = 0; g < 2; g++)
                ldmx4(Bh[g], st + G_BH + bLane + (uint32_t)(g*16*ROWB) + ko);

#pragma unroll
            for (int mf = 0; mf < 4; mf++)
#pragma unroll
                for (int nf = 0; nf < 4; nf++)
                    mma16816(acc[mf][nf], Ah[mf], &Bh[nf >> 1][(nf & 1) * 2]);

            if (useAL) {
                uint32_t Al[4][4];
#pragma unroll
                for (int mf = 0; mf < 4; mf++)
                    ldmx4(Al[mf], st + G_AL + aLane + (uint32_t)(mf*16*ROWB) + ko);
#pragma unroll
                for (int mf = 0; mf < 4; mf++)
#pragma unroll
                    for (int nf = 0; nf < 4; nf++)
                        mma16816(acc[mf][nf], Al[mf], &Bh[nf >> 1][(nf & 1) * 2]);
            }
        }
    }
    __syncthreads();

    // ---- epilogue ----
    const int l4 = lane >> 2;
    const int l2 = (lane & 3) * 2;
    const float scale = (MODE == 0 && blockIdx.z == 0) ? QSCALE : 1.0f;
#pragma unroll
    for (int mf = 0; mf < 4; mf++) {
#pragma unroll
        for (int half = 0; half < 2; half++) {
            const int m = mbase + wm*64 + mf*16 + half*8 + l4;
#pragma unroll
            for (int nf = 0; nf < 4; nf++) {
                const int n  = nbase + wn*32 + nf*8 + l2;
                const float c0 = acc[mf][nf][half*2 + 0] * scale;
                const float c1 = acc[mf][nf][half*2 + 1] * scale;
                if (MODE == 0) {
                    const int b  = m >> 11;
                    const int lr = m & 2047;
                    const int h  = n >> 6;
                    const int dk = n & 63;
                    const size_t off = ((size_t)(b*H_ + h)*L_ + lr)*DK_ + dk;
                    const uint32_t ph = hfpack(c0, c1);
                    if (z == 0) {
                        const float2 u = hfunpack(ph);
                        *(uint32_t*)(g_Qh + off) = ph;
                        *(uint32_t*)(g_Ql + off) = hfpack(c0 - u.x, c1 - u.y);
                    } else if (z == 1) {
                        *(uint32_t*)(g_Kh + off) = ph;
                    } else {
                        *(uint32_t*)(g_Vh + off) = ph;
                    }
                } else {
                    *(float2*)(Cout + (size_t)m * D_ + n) = make_float2(c0, c1);
                }
            }
        }
    }
}

// ---------------------------------------------------------------------------
// HMMA causal flash-attention, exp2 domain.
// S = (Qh+Ql) Kh (2-pass); P hi-only; O = Ph Vh (1-pass).
// Block = 128 queries of one (b,h); 8 warps x m16; 64-key double-buffered.
// ---------------------------------------------------------------------------
#define AROW 144
#define SQ_H 0
#define SQ_L (128*AROW)
#define SKV  (2*128*AROW)
#define A_KH 0
#define A_VH (64*AROW)
#define KV_STAGE (2*64*AROW)
#define ATTN_SMEM (SKV + 2*KV_STAGE)   // 73728

__global__ __launch_bounds__(256)
void attn_hmma()
{
    extern __shared__ char smem[];
    const uint32_t sb = smem_u32(smem);
    const int tid = threadIdx.x, wid = tid >> 5, lane = tid & 31;
    const int qt = (int)gridDim.x - 1 - (int)blockIdx.x;
    const int bh = blockIdx.y;

    const size_t hbase = (size_t)bh * L_ * DK_;
    const __half* Qhp = g_Qh + hbase + (size_t)qt*128*DK_;
    const __half* Qlp = g_Ql + hbase + (size_t)qt*128*DK_;
    const __half* Khp = g_Kh + hbase;
    const __half* Vhp = g_Vh + hbase;

    const int kbmax = 2*qt + 1;
    const int grow = tid >> 3;
    const int gc   = tid & 7;

    auto issue_kv = [&](int kb) {
        const uint32_t st = sb + SKV + (uint32_t)(kb & 1) * KV_STAGE;
        const size_t koff = (size_t)kb * 64 * DK_;
#pragma unroll
        for (int i = 0; i < 2; i++) {
            const int row = grow + i*32;
            const uint32_t d = (uint32_t)(row*AROW + gc*16);
            const size_t s = koff + (size_t)row*DK_ + gc*8;
            cpa16(st + A_KH + d, Khp + s);
            cpa16(st + A_VH + d, Vhp + s);
        }
        asm volatile("cp.async.commit_group;" ::: "memory");
    };

    {   // group 0: Q hi+lo + KV tile 0
#pragma unroll
        for (int i = 0; i < 4; i++) {
            const int row = grow + i*32;
            const uint32_t d = (uint32_t)(row*AROW + gc*16);
            const size_t s = (size_t)row*DK_ + gc*8;
            cpa16(sb + SQ_H + d, Qhp + s);
            cpa16(sb + SQ_L + d, Qlp + s);
        }
        const uint32_t st = sb + SKV;
#pragma unroll
        for (int i = 0; i < 2; i++) {
            const int row = grow + i*32;
            const uint32_t d = (uint32_t)(row*AROW + gc*16);
            const size_t s = (size_t)row*DK_ + gc*8;
            cpa16(st + A_KH + d, Khp + s);
            cpa16(st + A_VH + d, Vhp + s);
        }
        asm volatile("cp.async.commit_group;" ::: "memory");
    }

    const int t = lane >> 3, ri = lane & 7;
    const uint32_t aLane  = (uint32_t)((16*wid + (t&1)*8 + ri)*AROW + (t>>1)*16);
    const uint32_t bLaneK = (uint32_t)(((t>>1)*8 + ri)*AROW + (t&1)*16);
    const uint32_t vLane  = (uint32_t)((lane & 15)*AROW + (lane >> 4)*16);

    uint32_t Qha[4][4], Qla[4][4];
    float oacc[8][4];
#pragma unroll
    for (int j = 0; j < 8; j++)
#pragma unroll
        for (int q = 0; q < 4; q++) oacc[j][q] = 0.f;
    float m0 = -1e30f, m1 = -1e30f, l0 = 0.f, l1 = 0.f;

    for (int kb = 0; kb <= kbmax; kb++) {
        if (kb < kbmax) {
            issue_kv(kb + 1);
            asm volatile("cp.async.wait_group 1;" ::: "memory");
        } else {
            asm volatile("cp.async.wait_group 0;" ::: "memory");
        }
        __syncthreads();

        if (kb == 0) {
#pragma unroll
            for (int ks = 0; ks < 4; ks++) {
                ldmx4(Qha[ks], sb + SQ_H + aLane + (uint32_t)(ks*32));
                ldmx4(Qla[ks], sb + SQ_L + aLane + (uint32_t)(ks*32));
            }
        }

        const uint32_t st = sb + SKV + (uint32_t)(kb & 1) * KV_STAGE;
        const bool act = (64*kb) <= (128*qt + 16*wid + 15);
        if (act) {
            // ---- S = Q K^T (2-pass) ----
            float sacc[8][4];
#pragma unroll
            for (int j = 0; j < 8; j++)
#pragma unroll
                for (int q = 0; q < 4; q++) sacc[j][q] = 0.f;

#pragma unroll
            for (int ks = 0; ks < 4; ks++) {
                uint32_t KhF[4][4];
#pragma unroll
                for (int g = 0; g < 4; g++)
                    ldmx4(KhF[g], st + A_KH + bLaneK + (uint32_t)(g*16*AROW + ks*32));
#pragma unroll
                for (int j = 0; j < 8; j++) mma16816(sacc[j], Qha[ks], &KhF[j>>1][(j&1)*2]);
#pragma unroll
                for (int j = 0; j < 8; j++) mma16816(sacc[j], Qla[ks], &KhF[j>>1][(j&1)*2]);
            }

            // ---- causal mask (diagonal tiles only) ----
            if (kb >= 2*qt) {
                const int q0 = 128*qt + 16*wid + (lane >> 2);
#pragma unroll
                for (int j = 0; j < 8; j++) {
                    const int key = 64*kb + 8*j + (lane & 3)*2;
                    if (key     > q0    ) sacc[j][0] = -1e30f;
                    if (key + 1 > q0    ) sacc[j][1] = -1e30f;
                    if (key     > q0 + 8) sacc[j][2] = -1e30f;
                    if (key + 1 > q0 + 8) sacc[j][3] = -1e30f;
                }
            }

            // ---- online softmax (exp2) ----
            float mx0 = sacc[0][0], mx1 = sacc[0][2];
#pragma unroll
            for (int j = 0; j < 8; j++) {
                mx0 = fmaxf(mx0, fmaxf(sacc[j][0], sacc[j][1]));
                mx1 = fmaxf(mx1, fmaxf(sacc[j][2], sacc[j][3]));
            }
            mx0 = fmaxf(mx0, __shfl_xor_sync(0xffffffffu, mx0, 1));
            mx0 = fmaxf(mx0, __shfl_xor_sync(0xffffffffu, mx0, 2));
            mx1 = fmaxf(mx1, __shfl_xor_sync(0xffffffffu, mx1, 1));
            mx1 = fmaxf(mx1, __shfl_xor_sync(0xffffffffu, mx1, 2));
            const float mn0 = fmaxf(m0, mx0), mn1 = fmaxf(m1, mx1);
            const float f0 = exp2f(m0 - mn0), f1 = exp2f(m1 - mn1);
            m0 = mn0; m1 = mn1;
            float s0 = 0.f, s1 = 0.f;
#pragma unroll
            for (int j = 0; j < 8; j++) {
                sacc[j][0] = exp2f(sacc[j][0] - mn0);
                sacc[j][1] = exp2f(sacc[j][1] - mn0);
                sacc[j][2] = exp2f(sacc[j][2] - mn1);
                sacc[j][3] = exp2f(sacc[j][3] - mn1);
                s0 += sacc[j][0] + sacc[j][1];
                s1 += sacc[j][2] + sacc[j][3];
            }
            s0 += __shfl_xor_sync(0xffffffffu, s0, 1);
            s0 += __shfl_xor_sync(0xffffffffu, s0, 2);
            s1 += __shfl_xor_sync(0xffffffffu, s1, 1);
            s1 += __shfl_xor_sync(0xffffffffu, s1, 2);
            l0 = l0*f0 + s0; l1 = l1*f1 + s1;
#pragma unroll
            for (int j = 0; j < 8; j++) {
                oacc[j][0] *= f0; oacc[j][1] *= f0;
                oacc[j][2] *= f1; oacc[j][3] *= f1;
            }

            // ---- P: C-frag -> A-frag (hi only) ----
            uint32_t pah[4][4];
#pragma unroll
            for (int c = 0; c < 4; c++) {
                const int j0 = 2*c, j1 = 2*c + 1;
                pah[c][0] = hfpack(sacc[j0][0], sacc[j0][1]);
                pah[c][1] = hfpack(sacc[j0][2], sacc[j0][3]);
                pah[c][2] = hfpack(sacc[j1][0], sacc[j1][1]);
                pah[c][3] = hfpack(sacc[j1][2], sacc[j1][3]);
            }

            // ---- O += P V (1-pass) ----
#pragma unroll
            for (int ks = 0; ks < 4; ks++) {
                uint32_t VhF[4][4];
#pragma unroll
                for (int g = 0; g < 4; g++)
                    ldmx4t(VhF[g], st + A_VH + vLane + (uint32_t)(ks*16*AROW + g*32));
#pragma unroll
                for (int j = 0; j < 8; j++) mma16816(oacc[j], pah[ks], &VhF[j>>1][(j&1)*2]);
            }
        }
        __syncthreads();
    }

    // ---- epilogue: normalize + f16 split store to g_aoh/g_aol [B,L,D] ----
    const int b = bh >> 4, h = bh & 15;
    const float i0 = 1.f / l0, i1 = 1.f / l1;
    const int q0 = qt*128 + 16*wid + (lane >> 2);
#pragma unroll
    for (int j = 0; j < 8; j++) {
        const int col = h*64 + 8*j + (lane & 3)*2;
        {
            const float v0 = oacc[j][0]*i0, v1 = oacc[j][1]*i0;
            const uint32_t ph = hfpack(v0, v1);
            const float2 u = hfunpack(ph);
            const uint32_t pl = hfpack(v0 - u.x, v1 - u.y);
            const size_t o = ((size_t)(b*L_ + q0))*D_ + col;
            *(uint32_t*)(g_aoh + o) = ph;
            *(uint32_t*)(g_aol + o) = pl;
        }
        {
            const float v0 = oacc[j][2]*i1, v1 = oacc[j][3]*i1;
            const uint32_t ph = hfpack(v0, v1);
            const float2 u = hfunpack(ph);
            const uint32_t pl = hfpack(v0 - u.x, v1 - u.y);
            const size_t o = ((size_t)(b*L_ + q0 + 8))*D_ + col;
            *(uint32_t*)(g_aoh + o) = ph;
            *(uint32_t*)(g_aol + o) = pl;
        }
    }
}

// ---------------------------------------------------------------------------
extern "C" void kernel_launch(void* const* d_in, const int* in_sizes, int n_in,
                              void* d_out, int out_size)
{
    const float* x  = (const float*)d_in[0];
    const float* Wq = (const float*)d_in[1];
    const float* Wk = (const float*)d_in[2];
    const float* Wv = (const float*)d_in[3];
    const float* Wo = (const float*)d_in[4];
    float* out = (float*)d_out;

    cudaFuncSetAttribute(gemm_hmma<0>,
                         cudaFuncAttributeMaxDynamicSharedMemorySize, GEMM_SMEM);
    cudaFuncSetAttribute(gemm_hmma<1>,
                         cudaFuncAttributeMaxDynamicSharedMemorySize, GEMM_SMEM);
    cudaFuncSetAttribute(attn_hmma,
                         cudaFuncAttributeMaxDynamicSharedMemorySize, ATTN_SMEM);

    const int n4x = (B_*L_*D_) / 4;
    const int n4w = (D_*D_) / 4;

    xsplit_kernel<<<(n4x + 255)/256, 256>>>(x, n4x);
    wsplit_kernel<<<(4*n4w + 255)/256, 256>>>(Wq, Wk, Wv, Wo, n4w);

    // Q/K/V projections (Q 2-pass, K/V 1-pass; Q pre-scaled into exp2 domain)
    gemm_hmma<0><<<dim3(64, 8, 3), 256, GEMM_SMEM>>>(nullptr);

    // HMMA causal flash-attention (S 2-pass, PV 1-pass)
    attn_hmma<<<dim3(16, 64), 256, ATTN_SMEM>>>();

    // O-projection 2-pass -> fp32 out
    gemm_hmma<1><<<dim3(64, 8, 1), 256, GEMM_SMEM>>>(out);
}

// round 10
// speedup vs baseline: 5.7513x; 1.3252x over previous
#include <cuda_runtime.h>
#include <cuda_fp16.h>
#include <cstdint>

#define B_  4
#define L_  2048
#define D_  1024
#define H_  16
#define DK_ 64

// ---------------------------------------------------------------------------
// Scratch (static __device__ — no allocation allowed). Full f16 1-pass.
// ---------------------------------------------------------------------------
__device__ __half g_xh [B_*L_*D_];
__device__ __half g_Wh [4*D_*D_];      // Wq,Wk,Wv,Wo
__device__ __half g_aoh[B_*L_*D_];
__device__ __half g_Qh[B_*H_*L_*DK_];  // [B,H,L,dk]
__device__ __half g_Kh[B_*H_*L_*DK_];
__device__ __half g_Vh[B_*H_*L_*DK_];

// ---------------------------------------------------------------------------
// PTX helpers (compute_100-safe)
// ---------------------------------------------------------------------------
__device__ __forceinline__ uint32_t smem_u32(const void* p) {
    uint32_t a;
    asm("{ .reg .u64 t; cvta.to.shared.u64 t, %1; cvt.u32.u64 %0, t; }"
        : "=r"(a) : "l"(p));
    return a;
}
__device__ __forceinline__ void ldmx4(uint32_t* r, uint32_t a) {
    asm volatile("ldmatrix.sync.aligned.m8n8.x4.shared.b16 {%0,%1,%2,%3}, [%4];"
                 : "=r"(r[0]), "=r"(r[1]), "=r"(r[2]), "=r"(r[3]) : "r"(a));
}
__device__ __forceinline__ void ldmx4t(uint32_t* r, uint32_t a) {
    asm volatile("ldmatrix.sync.aligned.m8n8.x4.trans.shared.b16 {%0,%1,%2,%3}, [%4];"
                 : "=r"(r[0]), "=r"(r[1]), "=r"(r[2]), "=r"(r[3]) : "r"(a));
}
__device__ __forceinline__ void mma16816(float* c, const uint32_t* a, const uint32_t* b) {
    asm volatile("mma.sync.aligned.m16n8k16.row.col.f32.f16.f16.f32 "
                 "{%0,%1,%2,%3}, {%4,%5,%6,%7}, {%8,%9}, {%0,%1,%2,%3};"
                 : "+f"(c[0]), "+f"(c[1]), "+f"(c[2]), "+f"(c[3])
                 : "r"(a[0]), "r"(a[1]), "r"(a[2]), "r"(a[3]),
                   "r"(b[0]), "r"(b[1]));
}
__device__ __forceinline__ void cpa16(uint32_t s, const void* g) {
    asm volatile("cp.async.cg.shared.global [%0], [%1], 16;"
                 :: "r"(s), "l"(__cvta_generic_to_global(g)));
}
__device__ __forceinline__ uint32_t hfpack(float lo, float hi) {
    uint32_t d;
    asm("cvt.rn.f16x2.f32 %0, %1, %2;" : "=r"(d) : "f"(hi), "f"(lo));
    return d;
}

// ---------------------------------------------------------------------------
// converts: x -> f16, 4 weights -> f16
// ---------------------------------------------------------------------------
__global__ void xconv_kernel(const float* __restrict__ src, int n4)
{
    int i = blockIdx.x * blockDim.x + threadIdx.x;
    if (i >= n4) return;
    float4 v = ((const float4*)src)[i];
    ((__half2*)g_xh)[2*i]   = __halves2half2(__float2half(v.x), __float2half(v.y));
    ((__half2*)g_xh)[2*i+1] = __halves2half2(__float2half(v.z), __float2half(v.w));
}
__global__ void wconv_kernel(const float* __restrict__ w0, const float* __restrict__ w1,
                             const float* __restrict__ w2, const float* __restrict__ w3,
                             int n4w)
{
    int i = blockIdx.x * blockDim.x + threadIdx.x;
    if (i >= 4*n4w) return;
    const int sel = i / n4w;
    const int j   = i - sel * n4w;
    const float* src = (sel == 0) ? w0 : (sel == 1) ? w1 : (sel == 2) ? w2 : w3;
    float4 v = ((const float4*)src)[j];
    __half2* hi = (__half2*)(g_Wh + (size_t)sel * D_ * D_);
    hi[2*j]   = __halves2half2(__float2half(v.x), __float2half(v.y));
    hi[2*j+1] = __halves2half2(__float2half(v.z), __float2half(v.w));
}

// ---------------------------------------------------------------------------
// HMMA f16 GEMM (1-pass):  C[m,n] = sum_k A[m,k] * Wh[n,k]
// CTA 128x128, K-tile 32, 3-stage cp.async pipeline, 8 warps (64x32 each).
// MODE 0: A=x; z=0 -> Qh (scaled 0.125*log2e), z=1 -> Kh, z=2 -> Vh.
// MODE 1: A=AO, W=Wo -> fp32 Cout.
// ---------------------------------------------------------------------------
#define ROWB    80
#define G_AH    0
#define G_BH    (128*ROWB)             // 10240
#define G_STAGE (2*128*ROWB)           // 20480
#define GEMM_SMEM (3*G_STAGE)          // 61440

#define QSCALE 0.18033688011112042f    // 0.125 * log2(e)

template<int MODE>
__global__ __launch_bounds__(256)
void gemm_hmma(float* __restrict__ Cout)
{
    extern __shared__ char smem[];
    const uint32_t sb = smem_u32(smem);
    const int tid  = threadIdx.x;
    const int wid  = tid >> 5;
    const int lane = tid & 31;
    const int bm   = blockIdx.x;
    const int bn   = blockIdx.y;
    const int z    = (MODE == 0) ? blockIdx.z : 3;

    const __half* Agh = (MODE == 0) ? g_xh : g_aoh;
    const __half* Wgh = g_Wh + (size_t)z * D_ * D_;

    const int mbase = bm * 128;
    const int nbase = bn * 128;
    const int wm = wid >> 2;
    const int wn = wid & 3;

    const int t  = lane >> 3;
    const int ri = lane & 7;
    const uint32_t aLane = (uint32_t)((wm*64 + (t&1)*8 + ri) * ROWB + (t>>1)*16);
    const uint32_t bLane = (uint32_t)((wn*32 + (t>>1)*8 + ri) * ROWB + (t&1)*16);

    const int grow0 = tid >> 2;
    const int gc    = (tid & 3);
    const uint32_t so0 = (uint32_t)(grow0 * ROWB + gc * 16);
    const uint32_t so1 = so0 + 64u * ROWB;

    float acc[4][4][4];
#pragma unroll
    for (int i = 0; i < 4; i++)
#pragma unroll
        for (int j = 0; j < 4; j++)
#pragma unroll
            for (int q = 0; q < 4; q++) acc[i][j][q] = 0.f;

    const int NT = D_ / 32;

    auto issue_stage = [&](int kt) {
        const uint32_t st = sb + (uint32_t)(kt % 3) * G_STAGE;
        const int kcol = kt * 32;
        const size_t ga0 = (size_t)(mbase + grow0) * D_ + kcol + gc * 8;
        const size_t ga1 = ga0 + (size_t)64 * D_;
        const size_t gb0 = (size_t)(nbase + grow0) * D_ + kcol + gc * 8;
        const size_t gb1 = gb0 + (size_t)64 * D_;
        cpa16(st + G_AH + so0, Agh + ga0);
        cpa16(st + G_AH + so1, Agh + ga1);
        cpa16(st + G_BH + so0, Wgh + gb0);
        cpa16(st + G_BH + so1, Wgh + gb1);
        asm volatile("cp.async.commit_group;" ::: "memory");
    };

    issue_stage(0);
    issue_stage(1);

    for (int kt = 0; kt < NT; kt++) {
        if (kt == NT - 1) { asm volatile("cp.async.wait_group 0;" ::: "memory"); }
        else              { asm volatile("cp.async.wait_group 1;" ::: "memory"); }
        __syncthreads();
        if (kt + 2 < NT) issue_stage(kt + 2);

        const uint32_t st = sb + (uint32_t)(kt % 3) * G_STAGE;
#pragma unroll
        for (int ks = 0; ks < 2; ks++) {
            const uint32_t ko = (uint32_t)(ks * 32);
            uint32_t Ah[4][4], Bh[2][4];
#pragma unroll
            for (int mf = 0; mf < 4; mf++)
                ldmx4(Ah[mf], st + G_AH + aLane + (uint32_t)(mf*16*ROWB) + ko);
#pragma unroll
            for (int g = 0; g < 2; g++)
                ldmx4(Bh[g], st + G_BH + bLane + (uint32_t)(g*16*ROWB) + ko);

#pragma unroll
            for (int mf = 0; mf < 4; mf++)
#pragma unroll
                for (int nf = 0; nf < 4; nf++)
                    mma16816(acc[mf][nf], Ah[mf], &Bh[nf >> 1][(nf & 1) * 2]);
        }
    }
    __syncthreads();

    // ---- epilogue ----
    const int l4 = lane >> 2;
    const int l2 = (lane & 3) * 2;
    const float scale = (MODE == 0 && blockIdx.z == 0) ? QSCALE : 1.0f;
#pragma unroll
    for (int mf = 0; mf < 4; mf++) {
#pragma unroll
        for (int half = 0; half < 2; half++) {
            const int m = mbase + wm*64 + mf*16 + half*8 + l4;
#pragma unroll
            for (int nf = 0; nf < 4; nf++) {
                const int n  = nbase + wn*32 + nf*8 + l2;
                const float c0 = acc[mf][nf][half*2 + 0] * scale;
                const float c1 = acc[mf][nf][half*2 + 1] * scale;
                if (MODE == 0) {
                    const int b  = m >> 11;
                    const int lr = m & 2047;
                    const int h  = n >> 6;
                    const int dk = n & 63;
                    const size_t off = ((size_t)(b*H_ + h)*L_ + lr)*DK_ + dk;
                    __half* dst = (z == 0) ? g_Qh : (z == 1) ? g_Kh : g_Vh;
                    *(uint32_t*)(dst + off) = hfpack(c0, c1);
                } else {
                    *(float2*)(Cout + (size_t)m * D_ + n) = make_float2(c0, c1);
                }
            }
        }
    }
}

// ---------------------------------------------------------------------------
// HMMA causal flash-attention, f16 1-pass, exp2 domain.
// Block = 128 queries of one (b,h); 8 warps x m16; 64-key double-buffered.
// ---------------------------------------------------------------------------
#define AROW 144
#define SQ_H 0
#define SKV  (128*AROW)                // 18432
#define A_KH 0
#define A_VH (64*AROW)
#define KV_STAGE (2*64*AROW)           // 18432
#define ATTN_SMEM (SKV + 2*KV_STAGE)   // 55296

__global__ __launch_bounds__(256)
void attn_hmma()
{
    extern __shared__ char smem[];
    const uint32_t sb = smem_u32(smem);
    const int tid = threadIdx.x, wid = tid >> 5, lane = tid & 31;
    const int qt = (int)gridDim.x - 1 - (int)blockIdx.x;   // heavy first
    const int bh = blockIdx.y;

    const size_t hbase = (size_t)bh * L_ * DK_;
    const __half* Qhp = g_Qh + hbase + (size_t)qt*128*DK_;
    const __half* Khp = g_Kh + hbase;
    const __half* Vhp = g_Vh + hbase;

    const int kbmax = 2*qt + 1;
    const int grow = tid >> 3;
    const int gc   = tid & 7;

    auto issue_kv = [&](int kb) {
        const uint32_t st = sb + SKV + (uint32_t)(kb & 1) * KV_STAGE;
        const size_t koff = (size_t)kb * 64 * DK_;
#pragma unroll
        for (int i = 0; i < 2; i++) {
            const int row = grow + i*32;
            const uint32_t d = (uint32_t)(row*AROW + gc*16);
            const size_t s = koff + (size_t)row*DK_ + gc*8;
            cpa16(st + A_KH + d, Khp + s);
            cpa16(st + A_VH + d, Vhp + s);
        }
        asm volatile("cp.async.commit_group;" ::: "memory");
    };

    {   // group 0: Q + KV tile 0
#pragma unroll
        for (int i = 0; i < 4; i++) {
            const int row = grow + i*32;
            const uint32_t d = (uint32_t)(row*AROW + gc*16);
            cpa16(sb + SQ_H + d, Qhp + (size_t)row*DK_ + gc*8);
        }
        const uint32_t st = sb + SKV;
#pragma unroll
        for (int i = 0; i < 2; i++) {
            const int row = grow + i*32;
            const uint32_t d = (uint32_t)(row*AROW + gc*16);
            const size_t s = (size_t)row*DK_ + gc*8;
            cpa16(st + A_KH + d, Khp + s);
            cpa16(st + A_VH + d, Vhp + s);
        }
        asm volatile("cp.async.commit_group;" ::: "memory");
    }

    const int t = lane >> 3, ri = lane & 7;
    const uint32_t aLane  = (uint32_t)((16*wid + (t&1)*8 + ri)*AROW + (t>>1)*16);
    const uint32_t bLaneK = (uint32_t)(((t>>1)*8 + ri)*AROW + (t&1)*16);
    const uint32_t vLane  = (uint32_t)((lane & 15)*AROW + (lane >> 4)*16);

    uint32_t Qha[4][4];
    float oacc[8][4];
#pragma unroll
    for (int j = 0; j < 8; j++)
#pragma unroll
        for (int q = 0; q < 4; q++) oacc[j][q] = 0.f;
    float m0 = -1e30f, m1 = -1e30f, l0 = 0.f, l1 = 0.f;

    for (int kb = 0; kb <= kbmax; kb++) {
        if (kb < kbmax) {
            issue_kv(kb + 1);
            asm volatile("cp.async.wait_group 1;" ::: "memory");
        } else {
            asm volatile("cp.async.wait_group 0;" ::: "memory");
        }
        __syncthreads();

        if (kb == 0) {
#pragma unroll
            for (int ks = 0; ks < 4; ks++)
                ldmx4(Qha[ks], sb + SQ_H + aLane + (uint32_t)(ks*32));
        }

        const uint32_t st = sb + SKV + (uint32_t)(kb & 1) * KV_STAGE;
        const bool act = (64*kb) <= (128*qt + 16*wid + 15);
        if (act) {
            // ---- S = Q K^T (1-pass) ----
            float sacc[8][4];
#pragma unroll
            for (int j = 0; j < 8; j++)
#pragma unroll
                for (int q = 0; q < 4; q++) sacc[j][q] = 0.f;

#pragma unroll
            for (int ks = 0; ks < 4; ks++) {
                uint32_t KhF[4][4];
#pragma unroll
                for (int g = 0; g < 4; g++)
                    ldmx4(KhF[g], st + A_KH + bLaneK + (uint32_t)(g*16*AROW + ks*32));
#pragma unroll
                for (int j = 0; j < 8; j++) mma16816(sacc[j], Qha[ks], &KhF[j>>1][(j&1)*2]);
            }

            // ---- causal mask (diagonal tiles only) ----
            if (kb >= 2*qt) {
                const int q0 = 128*qt + 16*wid + (lane >> 2);
#pragma unroll
                for (int j = 0; j < 8; j++) {
                    const int key = 64*kb + 8*j + (lane & 3)*2;
                    if (key     > q0    ) sacc[j][0] = -1e30f;
                    if (key + 1 > q0    ) sacc[j][1] = -1e30f;
                    if (key     > q0 + 8) sacc[j][2] = -1e30f;
                    if (key + 1 > q0 + 8) sacc[j][3] = -1e30f;
                }
            }

            // ---- online softmax (exp2) ----
            float mx0 = sacc[0][0], mx1 = sacc[0][2];
#pragma unroll
            for (int j = 0; j < 8; j++) {
                mx0 = fmaxf(mx0, fmaxf(sacc[j][0], sacc[j][1]));
                mx1 = fmaxf(mx1, fmaxf(sacc[j][2], sacc[j][3]));
            }
            mx0 = fmaxf(mx0, __shfl_xor_sync(0xffffffffu, mx0, 1));
            mx0 = fmaxf(mx0, __shfl_xor_sync(0xffffffffu, mx0, 2));
            mx1 = fmaxf(mx1, __shfl_xor_sync(0xffffffffu, mx1, 1));
            mx1 = fmaxf(mx1, __shfl_xor_sync(0xffffffffu, mx1, 2));
            const float mn0 = fmaxf(m0, mx0), mn1 = fmaxf(m1, mx1);
            const float f0 = exp2f(m0 - mn0), f1 = exp2f(m1 - mn1);
            m0 = mn0; m1 = mn1;
            float s0 = 0.f, s1 = 0.f;
#pragma unroll
            for (int j = 0; j < 8; j++) {
                sacc[j][0] = exp2f(sacc[j][0] - mn0);
                sacc[j][1] = exp2f(sacc[j][1] - mn0);
                sacc[j][2] = exp2f(sacc[j][2] - mn1);
                sacc[j][3] = exp2f(sacc[j][3] - mn1);
                s0 += sacc[j][0] + sacc[j][1];
                s1 += sacc[j][2] + sacc[j][3];
            }
            s0 += __shfl_xor_sync(0xffffffffu, s0, 1);
            s0 += __shfl_xor_sync(0xffffffffu, s0, 2);
            s1 += __shfl_xor_sync(0xffffffffu, s1, 1);
            s1 += __shfl_xor_sync(0xffffffffu, s1, 2);
            l0 = l0*f0 + s0; l1 = l1*f1 + s1;
#pragma unroll
            for (int j = 0; j < 8; j++) {
                oacc[j][0] *= f0; oacc[j][1] *= f0;
                oacc[j][2] *= f1; oacc[j][3] *= f1;
            }

            // ---- P: C-frag -> A-frag (f16) ----
            uint32_t pah[4][4];
#pragma unroll
            for (int c = 0; c < 4; c++) {
                const int j0 = 2*c, j1 = 2*c + 1;
                pah[c][0] = hfpack(sacc[j0][0], sacc[j0][1]);
                pah[c][1] = hfpack(sacc[j0][2], sacc[j0][3]);
                pah[c][2] = hfpack(sacc[j1][0], sacc[j1][1]);
                pah[c][3] = hfpack(sacc[j1][2], sacc[j1][3]);
            }

            // ---- O += P V (1-pass) ----
#pragma unroll
            for (int ks = 0; ks < 4; ks++) {
                uint32_t VhF[4][4];
#pragma unroll
                for (int g = 0; g < 4; g++)
                    ldmx4t(VhF[g], st + A_VH + vLane + (uint32_t)(ks*16*AROW + g*32));
#pragma unroll
                for (int j = 0; j < 8; j++) mma16816(oacc[j], pah[ks], &VhF[j>>1][(j&1)*2]);
            }
        }
        __syncthreads();
    }

    // ---- epilogue: normalize + f16 store to g_aoh [B,L,D] ----
    const int b = bh >> 4, h = bh & 15;
    const float i0 = 1.f / l0, i1 = 1.f / l1;
    const int q0 = qt*128 + 16*wid + (lane >> 2);
#pragma unroll
    for (int j = 0; j < 8; j++) {
        const int col = h*64 + 8*j + (lane & 3)*2;
        *(uint32_t*)(g_aoh + ((size_t)(b*L_ + q0))*D_ + col) =
            hfpack(oacc[j][0]*i0, oacc[j][1]*i0);
        *(uint32_t*)(g_aoh + ((size_t)(b*L_ + q0 + 8))*D_ + col) =
            hfpack(oacc[j][2]*i1, oacc[j][3]*i1);
    }
}

// ---------------------------------------------------------------------------
extern "C" void kernel_launch(void* const* d_in, const int* in_sizes, int n_in,
                              void* d_out, int out_size)
{
    const float* x  = (const float*)d_in[0];
    const float* Wq = (const float*)d_in[1];
    const float* Wk = (const float*)d_in[2];
    const float* Wv = (const float*)d_in[3];
    const float* Wo = (const float*)d_in[4];
    float* out = (float*)d_out;

    cudaFuncSetAttribute(gemm_hmma<0>,
                         cudaFuncAttributeMaxDynamicSharedMemorySize, GEMM_SMEM);
    cudaFuncSetAttribute(gemm_hmma<1>,
                         cudaFuncAttributeMaxDynamicSharedMemorySize, GEMM_SMEM);
    cudaFuncSetAttribute(attn_hmma,
                         cudaFuncAttributeMaxDynamicSharedMemorySize, ATTN_SMEM);

    const int n4x = (B_*L_*D_) / 4;
    const int n4w = (D_*D_) / 4;

    xconv_kernel<<<(n4x + 255)/256, 256>>>(x, n4x);
    wconv_kernel<<<(4*n4w + 255)/256, 256>>>(Wq, Wk, Wv, Wo, n4w);

    // Q/K/V projections (1-pass; Q pre-scaled into exp2 domain)
    gemm_hmma<0><<<dim3(64, 8, 3), 256, GEMM_SMEM>>>(nullptr);

    // HMMA causal flash-attention (all 1-pass)
    attn_hmma<<<dim3(16, 64), 256, ATTN_SMEM>>>();

    // O-projection (1-pass) -> fp32 out
    gemm_hmma<1><<<dim3(64, 8, 1), 256, GEMM_SMEM>>>(out);
}

// round 11
// speedup vs baseline: 5.8577x; 1.0185x over previous
#include <cuda_runtime.h>
#include <cuda_fp16.h>
#include <cstdint>

#define B_  4
#define L_  2048
#define D_  1024
#define H_  16
#define DK_ 64

// ---------------------------------------------------------------------------
// Scratch (static __device__ — no allocation allowed). Full f16 1-pass.
// ---------------------------------------------------------------------------
__device__ __half g_xh [B_*L_*D_];
__device__ __half g_Wh [4*D_*D_];      // Wq,Wk,Wv,Wo
__device__ __half g_aoh[B_*L_*D_];
__device__ __half g_Qh[B_*H_*L_*DK_];  // [B,H,L,dk]
__device__ __half g_Kh[B_*H_*L_*DK_];
__device__ __half g_Vh[B_*H_*L_*DK_];

// ---------------------------------------------------------------------------
// PTX helpers (compute_100-safe)
// ---------------------------------------------------------------------------
__device__ __forceinline__ uint32_t smem_u32(const void* p) {
    uint32_t a;
    asm("{ .reg .u64 t; cvta.to.shared.u64 t, %1; cvt.u32.u64 %0, t; }"
        : "=r"(a) : "l"(p));
    return a;
}
__device__ __forceinline__ void ldmx4(uint32_t* r, uint32_t a) {
    asm volatile("ldmatrix.sync.aligned.m8n8.x4.shared.b16 {%0,%1,%2,%3}, [%4];"
                 : "=r"(r[0]), "=r"(r[1]), "=r"(r[2]), "=r"(r[3]) : "r"(a));
}
__device__ __forceinline__ void ldmx4t(uint32_t* r, uint32_t a) {
    asm volatile("ldmatrix.sync.aligned.m8n8.x4.trans.shared.b16 {%0,%1,%2,%3}, [%4];"
                 : "=r"(r[0]), "=r"(r[1]), "=r"(r[2]), "=r"(r[3]) : "r"(a));
}
__device__ __forceinline__ void mma16816(float* c, const uint32_t* a, const uint32_t* b) {
    asm volatile("mma.sync.aligned.m16n8k16.row.col.f32.f16.f16.f32 "
                 "{%0,%1,%2,%3}, {%4,%5,%6,%7}, {%8,%9}, {%0,%1,%2,%3};"
                 : "+f"(c[0]), "+f"(c[1]), "+f"(c[2]), "+f"(c[3])
                 : "r"(a[0]), "r"(a[1]), "r"(a[2]), "r"(a[3]),
                   "r"(b[0]), "r"(b[1]));
}
__device__ __forceinline__ void cpa16(uint32_t s, const void* g) {
    asm volatile("cp.async.cg.shared.global [%0], [%1], 16;"
                 :: "r"(s), "l"(__cvta_generic_to_global(g)));
}
__device__ __forceinline__ uint32_t hfpack(float lo, float hi) {
    uint32_t d;
    asm("cvt.rn.f16x2.f32 %0, %1, %2;" : "=r"(d) : "f"(hi), "f"(lo));
    return d;
}

// ---------------------------------------------------------------------------
// converts: x -> f16, 4 weights -> f16
// ---------------------------------------------------------------------------
__global__ void xconv_kernel(const float* __restrict__ src, int n4)
{
    int i = blockIdx.x * blockDim.x + threadIdx.x;
    if (i >= n4) return;
    float4 v = ((const float4*)src)[i];
    ((__half2*)g_xh)[2*i]   = __halves2half2(__float2half(v.x), __float2half(v.y));
    ((__half2*)g_xh)[2*i+1] = __halves2half2(__float2half(v.z), __float2half(v.w));
}
__global__ void wconv_kernel(const float* __restrict__ w0, const float* __restrict__ w1,
                             const float* __restrict__ w2, const float* __restrict__ w3,
                             int n4w)
{
    int i = blockIdx.x * blockDim.x + threadIdx.x;
    if (i >= 4*n4w) return;
    const int sel = i / n4w;
    const int j   = i - sel * n4w;
    const float* src = (sel == 0) ? w0 : (sel == 1) ? w1 : (sel == 2) ? w2 : w3;
    float4 v = ((const float4*)src)[j];
    __half2* hi = (__half2*)(g_Wh + (size_t)sel * D_ * D_);
    hi[2*j]   = __halves2half2(__float2half(v.x), __float2half(v.y));
    hi[2*j+1] = __halves2half2(__float2half(v.z), __float2half(v.w));
}

// ---------------------------------------------------------------------------
// HMMA f16 GEMM (1-pass, verified R9):  C[m,n] = sum_k A[m,k] * Wh[n,k]
// CTA 128x128, K-tile 32, 3-stage cp.async pipeline, 8 warps (64x32 each).
// ---------------------------------------------------------------------------
#define ROWB    80
#define G_AH    0
#define G_BH    (128*ROWB)
#define G_STAGE (2*128*ROWB)           // 20480
#define GEMM_SMEM (3*G_STAGE)          // 61440

#define QSCALE 0.18033688011112042f    // 0.125 * log2(e)

template<int MODE>
__global__ __launch_bounds__(256)
void gemm_hmma(float* __restrict__ Cout)
{
    extern __shared__ char smem[];
    const uint32_t sb = smem_u32(smem);
    const int tid  = threadIdx.x;
    const int wid  = tid >> 5;
    const int lane = tid & 31;
    const int bm   = blockIdx.x;
    const int bn   = blockIdx.y;
    const int z    = (MODE == 0) ? blockIdx.z : 3;

    const __half* Agh = (MODE == 0) ? g_xh : g_aoh;
    const __half* Wgh = g_Wh + (size_t)z * D_ * D_;

    const int mbase = bm * 128;
    const int nbase = bn * 128;
    const int wm = wid >> 2;
    const int wn = wid & 3;

    const int t  = lane >> 3;
    const int ri = lane & 7;
    const uint32_t aLane = (uint32_t)((wm*64 + (t&1)*8 + ri) * ROWB + (t>>1)*16);
    const uint32_t bLane = (uint32_t)((wn*32 + (t>>1)*8 + ri) * ROWB + (t&1)*16);

    const int grow0 = tid >> 2;
    const int gc    = (tid & 3);
    const uint32_t so0 = (uint32_t)(grow0 * ROWB + gc * 16);
    const uint32_t so1 = so0 + 64u * ROWB;

    float acc[4][4][4];
#pragma unroll
    for (int i = 0; i < 4; i++)
#pragma unroll
        for (int j = 0; j < 4; j++)
#pragma unroll
            for (int q = 0; q < 4; q++) acc[i][j][q] = 0.f;

    const int NT = D_ / 32;

    auto issue_stage = [&](int kt) {
        const uint32_t st = sb + (uint32_t)(kt % 3) * G_STAGE;
        const int kcol = kt * 32;
        const size_t ga0 = (size_t)(mbase + grow0) * D_ + kcol + gc * 8;
        const size_t ga1 = ga0 + (size_t)64 * D_;
        const size_t gb0 = (size_t)(nbase + grow0) * D_ + kcol + gc * 8;
        const size_t gb1 = gb0 + (size_t)64 * D_;
        cpa16(st + G_AH + so0, Agh + ga0);
        cpa16(st + G_AH + so1, Agh + ga1);
        cpa16(st + G_BH + so0, Wgh + gb0);
        cpa16(st + G_BH + so1, Wgh + gb1);
        asm volatile("cp.async.commit_group;" ::: "memory");
    };

    issue_stage(0);
    issue_stage(1);

    for (int kt = 0; kt < NT; kt++) {
        if (kt == NT - 1) { asm volatile("cp.async.wait_group 0;" ::: "memory"); }
        else              { asm volatile("cp.async.wait_group 1;" ::: "memory"); }
        __syncthreads();
        if (kt + 2 < NT) issue_stage(kt + 2);

        const uint32_t st = sb + (uint32_t)(kt % 3) * G_STAGE;
#pragma unroll
        for (int ks = 0; ks < 2; ks++) {
            const uint32_t ko = (uint32_t)(ks * 32);
            uint32_t Ah[4][4], Bh[2][4];
#pragma unroll
            for (int mf = 0; mf < 4; mf++)
                ldmx4(Ah[mf], st + G_AH + aLane + (uint32_t)(mf*16*ROWB) + ko);
#pragma unroll
            for (int g = 0; g < 2; g++)
                ldmx4(Bh[g], st + G_BH + bLane + (uint32_t)(g*16*ROWB) + ko);

#pragma unroll
            for (int mf = 0; mf < 4; mf++)
#pragma unroll
                for (int nf = 0; nf < 4; nf++)
                    mma16816(acc[mf][nf], Ah[mf], &Bh[nf >> 1][(nf & 1) * 2]);
        }
    }
    __syncthreads();

    // ---- epilogue ----
    const int l4 = lane >> 2;
    const int l2 = (lane & 3) * 2;
    const float scale = (MODE == 0 && blockIdx.z == 0) ? QSCALE : 1.0f;
#pragma unroll
    for (int mf = 0; mf < 4; mf++) {
#pragma unroll
        for (int half = 0; half < 2; half++) {
            const int m = mbase + wm*64 + mf*16 + half*8 + l4;
#pragma unroll
            for (int nf = 0; nf < 4; nf++) {
                const int n  = nbase + wn*32 + nf*8 + l2;
                const float c0 = acc[mf][nf][half*2 + 0] * scale;
                const float c1 = acc[mf][nf][half*2 + 1] * scale;
                if (MODE == 0) {
                    const int b  = m >> 11;
                    const int lr = m & 2047;
                    const int h  = n >> 6;
                    const int dk = n & 63;
                    const size_t off = ((size_t)(b*H_ + h)*L_ + lr)*DK_ + dk;
                    __half* dst = (z == 0) ? g_Qh : (z == 1) ? g_Kh : g_Vh;
                    *(uint32_t*)(dst + off) = hfpack(c0, c1);
                } else {
                    *(float2*)(Cout + (size_t)m * D_ + n) = make_float2(c0, c1);
                }
            }
        }
    }
}

// ---------------------------------------------------------------------------
// HMMA causal flash-attention, f16 1-pass, exp2 domain.
// 128-thread CTAs (4 warps) x 64-query tiles -> 4 CTAs/SM = 4 independent
// phase domains covering the tensor pipe during softmax. 2-stage KV.
// ---------------------------------------------------------------------------
#define AROW 144
#define SQ_H 0
#define SKV  (64*AROW)                 // 9216
#define A_KH 0
#define A_VH (64*AROW)
#define KV_STAGE (2*64*AROW)           // 18432
#define ATTN_SMEM (SKV + 2*KV_STAGE)   // 46080

__global__ __launch_bounds__(128, 4)
void attn_hmma()
{
    extern __shared__ char smem[];
    const uint32_t sb = smem_u32(smem);
    const int tid = threadIdx.x, wid = tid >> 5, lane = tid & 31;
    const int qt = (int)gridDim.x - 1 - (int)blockIdx.x;   // heavy first
    const int bh = blockIdx.y;

    const size_t hbase = (size_t)bh * L_ * DK_;
    const __half* Qhp = g_Qh + hbase + (size_t)qt*64*DK_;
    const __half* Khp = g_Kh + hbase;
    const __half* Vhp = g_Vh + hbase;

    const int kbmax = qt;
    const int grow = tid >> 3;         // 0..15
    const int gc   = tid & 7;

    auto issue_kv = [&](int kb) {
        const uint32_t st = sb + SKV + (uint32_t)(kb & 1) * KV_STAGE;
        const size_t koff = (size_t)kb * 64 * DK_;
#pragma unroll
        for (int i = 0; i < 4; i++) {
            const int row = grow + i*16;
            const uint32_t d = (uint32_t)(row*AROW + gc*16);
            const size_t s = koff + (size_t)row*DK_ + gc*8;
            cpa16(st + A_KH + d, Khp + s);
            cpa16(st + A_VH + d, Vhp + s);
        }
        asm volatile("cp.async.commit_group;" ::: "memory");
    };

    {   // group 0: Q (64 rows) + KV tile 0
#pragma unroll
        for (int i = 0; i < 4; i++) {
            const int row = grow + i*16;
            const uint32_t d = (uint32_t)(row*AROW + gc*16);
            cpa16(sb + SQ_H + d, Qhp + (size_t)row*DK_ + gc*8);
        }
        const uint32_t st = sb + SKV;
#pragma unroll
        for (int i = 0; i < 4; i++) {
            const int row = grow + i*16;
            const uint32_t d = (uint32_t)(row*AROW + gc*16);
            const size_t s = (size_t)row*DK_ + gc*8;
            cpa16(st + A_KH + d, Khp + s);
            cpa16(st + A_VH + d, Vhp + s);
        }
        asm volatile("cp.async.commit_group;" ::: "memory");
    }

    const int t = lane >> 3, ri = lane & 7;
    const uint32_t aLane  = (uint32_t)((16*wid + (t&1)*8 + ri)*AROW + (t>>1)*16);
    const uint32_t bLaneK = (uint32_t)(((t>>1)*8 + ri)*AROW + (t&1)*16);
    const uint32_t vLane  = (uint32_t)((lane & 15)*AROW + (lane >> 4)*16);

    uint32_t Qha[4][4];
    float oacc[8][4];
#pragma unroll
    for (int j = 0; j < 8; j++)
#pragma unroll
        for (int q = 0; q < 4; q++) oacc[j][q] = 0.f;
    float m0 = -1e30f, m1 = -1e30f, l0 = 0.f, l1 = 0.f;

    for (int kb = 0; kb <= kbmax; kb++) {
        if (kb < kbmax) {
            issue_kv(kb + 1);
            asm volatile("cp.async.wait_group 1;" ::: "memory");
        } else {
            asm volatile("cp.async.wait_group 0;" ::: "memory");
        }
        __syncthreads();

        if (kb == 0) {
#pragma unroll
            for (int ks = 0; ks < 4; ks++)
                ldmx4(Qha[ks], sb + SQ_H + aLane + (uint32_t)(ks*32));
        }

        const uint32_t st = sb + SKV + (uint32_t)(kb & 1) * KV_STAGE;

        // ---- S = Q K^T (1-pass) ----
        float sacc[8][4];
#pragma unroll
        for (int j = 0; j < 8; j++)
#pragma unroll
            for (int q = 0; q < 4; q++) sacc[j][q] = 0.f;

#pragma unroll
        for (int ks = 0; ks < 4; ks++) {
            uint32_t KhF[4][4];
#pragma unroll
            for (int g = 0; g < 4; g++)
                ldmx4(KhF[g], st + A_KH + bLaneK + (uint32_t)(g*16*AROW + ks*32));
#pragma unroll
            for (int j = 0; j < 8; j++) mma16816(sacc[j], Qha[ks], &KhF[j>>1][(j&1)*2]);
        }

        // ---- causal mask (single diagonal tile kb == qt) ----
        if (kb == qt) {
            const int q0 = 64*qt + 16*wid + (lane >> 2);
#pragma unroll
            for (int j = 0; j < 8; j++) {
                const int key = 64*kb + 8*j + (lane & 3)*2;
                if (key     > q0    ) sacc[j][0] = -1e30f;
                if (key + 1 > q0    ) sacc[j][1] = -1e30f;
                if (key     > q0 + 8) sacc[j][2] = -1e30f;
                if (key + 1 > q0 + 8) sacc[j][3] = -1e30f;
            }
        }

        // ---- online softmax (exp2): max -> rescale -> exp -> pack -> PV ----
        float mx0 = sacc[0][0], mx1 = sacc[0][2];
#pragma unroll
        for (int j = 0; j < 8; j++) {
            mx0 = fmaxf(mx0, fmaxf(sacc[j][0], sacc[j][1]));
            mx1 = fmaxf(mx1, fmaxf(sacc[j][2], sacc[j][3]));
        }
        mx0 = fmaxf(mx0, __shfl_xor_sync(0xffffffffu, mx0, 1));
        mx0 = fmaxf(mx0, __shfl_xor_sync(0xffffffffu, mx0, 2));
        mx1 = fmaxf(mx1, __shfl_xor_sync(0xffffffffu, mx1, 1));
        mx1 = fmaxf(mx1, __shfl_xor_sync(0xffffffffu, mx1, 2));
        const float mn0 = fmaxf(m0, mx0), mn1 = fmaxf(m1, mx1);
        const float f0 = exp2f(m0 - mn0), f1 = exp2f(m1 - mn1);
        m0 = mn0; m1 = mn1;

        // O-rescale, skipped (exactly) when the whole warp's maxima held
        if (!__all_sync(0xffffffffu, (f0 == 1.f) && (f1 == 1.f))) {
#pragma unroll
            for (int j = 0; j < 8; j++) {
                oacc[j][0] *= f0; oacc[j][1] *= f0;
                oacc[j][2] *= f1; oacc[j][3] *= f1;
            }
        }

        float s0 = 0.f, s1 = 0.f;
#pragma unroll
        for (int j = 0; j < 8; j++) {
            sacc[j][0] = exp2f(sacc[j][0] - mn0);
            sacc[j][1] = exp2f(sacc[j][1] - mn0);
            sacc[j][2] = exp2f(sacc[j][2] - mn1);
            sacc[j][3] = exp2f(sacc[j][3] - mn1);
            s0 += sacc[j][0] + sacc[j][1];
            s1 += sacc[j][2] + sacc[j][3];
        }

        // P: C-frag -> A-frag (f16)
        uint32_t pah[4][4];
#pragma unroll
        for (int c = 0; c < 4; c++) {
            const int j0 = 2*c, j1 = 2*c + 1;
            pah[c][0] = hfpack(sacc[j0][0], sacc[j0][1]);
            pah[c][1] = hfpack(sacc[j0][2], sacc[j0][3]);
            pah[c][2] = hfpack(sacc[j1][0], sacc[j1][1]);
            pah[c][3] = hfpack(sacc[j1][2], sacc[j1][3]);
        }

        // O += P V (issue tensor work before the sum-shfl chain)
#pragma unroll
        for (int ks = 0; ks < 4; ks++) {
            uint32_t VhF[4][4];
#pragma unroll
            for (int g = 0; g < 4; g++)
                ldmx4t(VhF[g], st + A_VH + vLane + (uint32_t)(ks*16*AROW + g*32));
#pragma unroll
            for (int j = 0; j < 8; j++) mma16816(oacc[j], pah[ks], &VhF[j>>1][(j&1)*2]);
        }

        // deferred row-sum reduction + l update (overlaps PV latency)
        s0 += __shfl_xor_sync(0xffffffffu, s0, 1);
        s0 += __shfl_xor_sync(0xffffffffu, s0, 2);
        s1 += __shfl_xor_sync(0xffffffffu, s1, 1);
        s1 += __shfl_xor_sync(0xffffffffu, s1, 2);
        l0 = l0*f0 + s0; l1 = l1*f1 + s1;

        __syncthreads();
    }

    // ---- epilogue: normalize + f16 store to g_aoh [B,L,D] ----
    const int b = bh >> 4, h = bh & 15;
    const float i0 = 1.f / l0, i1 = 1.f / l1;
    const int q0 = qt*64 + 16*wid + (lane >> 2);
#pragma unroll
    for (int j = 0; j < 8; j++) {
        const int col = h*64 + 8*j + (lane & 3)*2;
        *(uint32_t*)(g_aoh + ((size_t)(b*L_ + q0))*D_ + col) =
            hfpack(oacc[j][0]*i0, oacc[j][1]*i0);
        *(uint32_t*)(g_aoh + ((size_t)(b*L_ + q0 + 8))*D_ + col) =
            hfpack(oacc[j][2]*i1, oacc[j][3]*i1);
    }
}

// ---------------------------------------------------------------------------
extern "C" void kernel_launch(void* const* d_in, const int* in_sizes, int n_in,
                              void* d_out, int out_size)
{
    const float* x  = (const float*)d_in[0];
    const float* Wq = (const float*)d_in[1];
    const float* Wk = (const float*)d_in[2];
    const float* Wv = (const float*)d_in[3];
    const float* Wo = (const float*)d_in[4];
    float* out = (float*)d_out;

    cudaFuncSetAttribute(gemm_hmma<0>,
                         cudaFuncAttributeMaxDynamicSharedMemorySize, GEMM_SMEM);
    cudaFuncSetAttribute(gemm_hmma<1>,
                         cudaFuncAttributeMaxDynamicSharedMemorySize, GEMM_SMEM);
    cudaFuncSetAttribute(attn_hmma,
                         cudaFuncAttributeMaxDynamicSharedMemorySize, ATTN_SMEM);

    const int n4x = (B_*L_*D_) / 4;
    const int n4w = (D_*D_) / 4;

    xconv_kernel<<<(n4x + 255)/256, 256>>>(x, n4x);
    wconv_kernel<<<(4*n4w + 255)/256, 256>>>(Wq, Wk, Wv, Wo, n4w);

    // Q/K/V projections (1-pass; Q pre-scaled into exp2 domain)
    gemm_hmma<0><<<dim3(64, 8, 3), 256, GEMM_SMEM>>>(nullptr);

    // HMMA causal flash-attention: 64-query CTAs, 4 phase domains/SM
    attn_hmma<<<dim3(32, 64), 128, ATTN_SMEM>>>();

    // O-projection (1-pass) -> fp32 out
    gemm_hmma<1><<<dim3(64, 8, 1), 256, GEMM_SMEM>>>(out);
}